// round 6
// baseline (speedup 1.0000x reference)
#include <cuda_runtime.h>
#include <cuda_fp16.h>

// ---------------------------------------------------------------------------
// Problem constants
// ---------------------------------------------------------------------------
constexpr int Bc  = 8;
constexpr int Lc  = 4096;
constexpr int NH  = 16;
constexpr int HD  = 64;
constexpr int HID = 1024;
constexpr int MTOK = Bc * Lc;       // 32768
constexpr int Kdim = 1024;
constexpr int NQK  = 2048;          // fused Q|K output width

// GEMM tiling
constexpr int BM = 128, BN = 128, BK = 64;
constexpr int NC = Kdim / BK;       // 16 k-chunks
// stage layout (bytes): Ahi 16K | Bhi 16K | Blo 16K
constexpr int ST_A   = 0;
constexpr int ST_BHI = 16384;
constexpr int ST_BLO = 32768;
constexpr int STAGE_BYTES = 49152;
constexpr int NSLOT = 4;            // loads run 3 chunks ahead
constexpr int SMEM_REQ = NSLOT * STAGE_BYTES + 1024;   // ~197 KB

// ---------------------------------------------------------------------------
// Scratch (device globals: no allocation allowed)
// ---------------------------------------------------------------------------
__device__ float g_qk [(size_t)MTOK * NQK];    // fused Q|K output (fp32)
__device__ float g_ak [Bc * HID];
__device__ float g_av [Bc * HID];
__device__ float g_bqk[NQK];                   // concat bias
__device__ __half g_xhi [(size_t)MTOK * HID];
__device__ __half g_ahi [(size_t)MTOK * HID];  // attention out (fp16 hi)
__device__ __half g_wqkT_hi[(size_t)NQK * Kdim], g_wqkT_lo[(size_t)NQK * Kdim];
__device__ __half g_woT_hi [(size_t)Kdim * HID], g_woT_lo [(size_t)Kdim * HID];

// ---------------------------------------------------------------------------
// helpers
// ---------------------------------------------------------------------------
__device__ __forceinline__ unsigned smem_u32(const void* p) {
    unsigned a;
    asm("{ .reg .u64 t; cvta.to.shared.u64 t, %1; cvt.u32.u64 %0, t; }"
        : "=r"(a) : "l"(p));
    return a;
}
__device__ __forceinline__ void cp16(unsigned saddr, const void* g) {
    asm volatile("cp.async.cg.shared.global [%0], [%1], 16;\n"
                 :: "r"(saddr), "l"(g));
}
#define CP_COMMIT() asm volatile("cp.async.commit_group;\n" ::: "memory")
#define CP_WAIT2()  asm volatile("cp.async.wait_group 2;\n" ::: "memory")
#define CP_WAIT0()  asm volatile("cp.async.wait_group 0;\n" ::: "memory")

__device__ __forceinline__ void ldsm4(unsigned& r0, unsigned& r1,
                                      unsigned& r2, unsigned& r3, unsigned a) {
    asm volatile("ldmatrix.sync.aligned.m8n8.x4.shared.b16 {%0,%1,%2,%3}, [%4];"
                 : "=r"(r0), "=r"(r1), "=r"(r2), "=r"(r3) : "r"(a));
}
__device__ __forceinline__ void mma16816(float* c, const unsigned* a,
                                         const unsigned* b) {
    asm volatile(
        "mma.sync.aligned.m16n8k16.row.col.f32.f16.f16.f32 "
        "{%0,%1,%2,%3}, {%4,%5,%6,%7}, {%8,%9}, {%0,%1,%2,%3};"
        : "+f"(c[0]), "+f"(c[1]), "+f"(c[2]), "+f"(c[3])
        : "r"(a[0]), "r"(a[1]), "r"(a[2]), "r"(a[3]), "r"(b[0]), "r"(b[1]));
}

// ---------------------------------------------------------------------------
// 2-pass split-fp16 HMMA GEMM: C[M, N] = Ahi @ (Bhi + Blo)^T + bias
// B operands transposed: [N, K] K-major. CTA 128x128, BK=64, 8 warps,
// warp tile 64x32, 4-slot cp.async pipeline, loads 3 ahead, 1 barrier/chunk.
// Invariant: at top of iter c, commits issued = 3 + c; wait_group 2 leaves
// <= 2 pending => >= c+1 groups retired => chunk c's data is in smem.
// Tail iterations commit EMPTY groups to keep the invariant exact.
// ---------------------------------------------------------------------------
__global__ __launch_bounds__(256, 1)
void gemm_mma2(const __half* __restrict__ Ahi,
               const __half* __restrict__ Bhi, const __half* __restrict__ Blo,
               const float* __restrict__ bias, float* __restrict__ C, int ldc)
{
    extern __shared__ char smem_raw[];
    const unsigned sbase = (smem_u32(smem_raw) + 1023u) & ~1023u;
    const int tid  = threadIdx.x;
    const int wid  = tid >> 5;
    const int lane = tid & 31;
    const int row0 = blockIdx.y * BM;
    const int col0 = blockIdx.x * BN;

    auto load_chunk = [&](int c, int slot) {
        const unsigned sa = sbase + slot * STAGE_BYTES;
        const int kt = c * BK;
        #pragma unroll
        for (int i = 0; i < 4; ++i) {
            int v = tid + i * 256;          // 0..1023
            int r = v >> 3, u = v & 7;      // row 0..127, 16B unit 0..7
            unsigned bo = (unsigned)(r * 128 + u * 16);
            unsigned so = bo ^ ((bo >> 3) & 0x70);   // SW128
            size_t goA = (size_t)(row0 + r) * Kdim + kt + u * 8;
            size_t goB = (size_t)(col0 + r) * Kdim + kt + u * 8;
            cp16(sa + ST_A   + so, Ahi + goA);
            cp16(sa + ST_BHI + so, Bhi + goB);
            cp16(sa + ST_BLO + so, Blo + goB);
        }
        CP_COMMIT();
    };

    // per-lane ldmatrix address components
    const int mrow0 = (wid >> 2) * 64;      // warp M offset
    const int nrow0 = (wid & 3) * 32;       // warp N offset
    const unsigned rtA  = (lane & 7) + ((lane >> 3) & 1) * 8;
    const unsigned s16A = ((lane >> 4) & 1) * 16;
    const unsigned rtB  = (lane & 7) + ((lane >> 4) & 1) * 8;
    const unsigned s16B = ((lane >> 3) & 1) * 16;
    const unsigned xorv = (lane & 7) * 16;

    float acc[4][4][4];
    #pragma unroll
    for (int mi = 0; mi < 4; ++mi)
        #pragma unroll
        for (int ni = 0; ni < 4; ++ni)
            #pragma unroll
            for (int r = 0; r < 4; ++r) acc[mi][ni][r] = 0.f;

    load_chunk(0, 0);
    load_chunk(1, 1);
    load_chunk(2, 2);

    for (int c = 0; c < NC; ++c) {
        const int slot = c & 3;
        CP_WAIT2();                      // chunk c guaranteed landed
        __syncthreads();                 // slot (c+3)&3 free (last used @ c-1)
        if (c + 3 < NC) load_chunk(c + 3, (c + 3) & 3);
        else            CP_COMMIT();     // empty group keeps invariant exact

        const unsigned sa   = sbase + slot * STAGE_BYTES;
        const unsigned pA   = sa + ST_A   + (mrow0 + rtA) * 128;
        const unsigned pBhi = sa + ST_BHI + (nrow0 + rtB) * 128;
        const unsigned pBlo = sa + ST_BLO + (nrow0 + rtB) * 128;

        #pragma unroll
        for (int kk = 0; kk < 4; ++kk) {
            const unsigned colA = ((unsigned)(kk * 32) + s16A) ^ xorv;
            const unsigned colB = ((unsigned)(kk * 32) + s16B) ^ xorv;
            unsigned ah[4][4], bh[2][4], bl[2][4];
            #pragma unroll
            for (int mi = 0; mi < 4; ++mi)
                ldsm4(ah[mi][0], ah[mi][1], ah[mi][2], ah[mi][3],
                      pA + mi * 2048 + colA);
            #pragma unroll
            for (int nb = 0; nb < 2; ++nb) {
                ldsm4(bh[nb][0], bh[nb][1], bh[nb][2], bh[nb][3],
                      pBhi + nb * 2048 + colB);
                ldsm4(bl[nb][0], bl[nb][1], bl[nb][2], bl[nb][3],
                      pBlo + nb * 2048 + colB);
            }
            #pragma unroll
            for (int mi = 0; mi < 4; ++mi)
                #pragma unroll
                for (int ni = 0; ni < 4; ++ni) {
                    const unsigned* bhp = &bh[ni >> 1][(ni & 1) * 2];
                    const unsigned* blp = &bl[ni >> 1][(ni & 1) * 2];
                    mma16816(acc[mi][ni], ah[mi], bhp);   // A*Bhi
                    mma16816(acc[mi][ni], ah[mi], blp);   // A*Blo
                }
        }
    }
    CP_WAIT0();

    // epilogue: acc + bias -> C
    #pragma unroll
    for (int ni = 0; ni < 4; ++ni) {
        const int cc = col0 + nrow0 + ni * 8 + (lane & 3) * 2;
        const float b0 = bias[cc], b1 = bias[cc + 1];
        #pragma unroll
        for (int mi = 0; mi < 4; ++mi) {
            const int r = row0 + mrow0 + mi * 16 + (lane >> 2);
            float2 v0 = make_float2(acc[mi][ni][0] + b0, acc[mi][ni][1] + b1);
            float2 v1 = make_float2(acc[mi][ni][2] + b0, acc[mi][ni][3] + b1);
            *(float2*)(C + (size_t)r * ldc + cc)       = v0;
            *(float2*)(C + (size_t)(r + 8) * ldc + cc) = v1;
        }
    }
}

// ---------------------------------------------------------------------------
// fp32 -> fp16 convert (hi only), vectorized
// ---------------------------------------------------------------------------
__global__ __launch_bounds__(256)
void to_half(const float* __restrict__ in, __half* __restrict__ out, int n4)
{
    int i = blockIdx.x * blockDim.x + threadIdx.x;
    if (i >= n4) return;
    float4 v = ((const float4*)in)[i];
    __half2* op = (__half2*)(out + (size_t)i * 4);
    op[0] = __half2(__float2half_rn(v.x), __float2half_rn(v.y));
    op[1] = __half2(__float2half_rn(v.z), __float2half_rn(v.w));
}

// ---------------------------------------------------------------------------
// W [K,N] fp32 -> W^T hi/lo fp16 [N,K]
// ---------------------------------------------------------------------------
__global__ __launch_bounds__(256)
void transpose_split(const float* __restrict__ W,
                     __half* __restrict__ ThT, __half* __restrict__ TlT)
{
    __shared__ float t[32][33];
    const int tx = threadIdx.x, ty = threadIdx.y;   // (32, 8)
    const int n0 = blockIdx.x * 32, k0 = blockIdx.y * 32;
    #pragma unroll
    for (int i = 0; i < 32; i += 8)
        t[ty + i][tx] = W[(size_t)(k0 + ty + i) * HID + n0 + tx];
    __syncthreads();
    #pragma unroll
    for (int i = 0; i < 32; i += 8) {
        float v = t[tx][ty + i];
        __half h = __float2half_rn(v);
        __half l = __float2half_rn(v - __half2float(h));
        ThT[(size_t)(n0 + ty + i) * Kdim + k0 + tx] = h;
        TlT[(size_t)(n0 + ty + i) * Kdim + k0 + tx] = l;
    }
}

// ---------------------------------------------------------------------------
// Tiny projections: ak = ax@WK + bK, av = ax@WV + bV (fp32, 8x1024 each)
// ---------------------------------------------------------------------------
__global__ __launch_bounds__(256)
void proj_small(const float* __restrict__ ax,
                const float* __restrict__ WK, const float* __restrict__ WKb,
                const float* __restrict__ WV, const float* __restrict__ WVb)
{
    __shared__ float xs[HID];
    const int sel = blockIdx.x >> 5;
    const int bb  = (blockIdx.x >> 2) & 7;
    const int n   = ((blockIdx.x & 3) << 8) + threadIdx.x;
    for (int i = threadIdx.x; i < HID; i += 256) xs[i] = ax[bb * HID + i];
    __syncthreads();
    const float* W    = sel ? WV  : WK;
    const float* bias = sel ? WVb : WKb;
    float acc = 0.f;
    #pragma unroll 8
    for (int kk = 0; kk < HID; ++kk)
        acc = fmaf(xs[kk], W[(size_t)kk * HID + n], acc);
    float* o = sel ? g_av : g_ak;
    o[bb * HID + n] = acc + bias[n];
}

// ---------------------------------------------------------------------------
// Attention on fused qk buffer (row stride NQK), emits fp16 output.
// ---------------------------------------------------------------------------
__global__ __launch_bounds__(256)
void attn_kernel(const float* __restrict__ qk, __half* __restrict__ ahi)
{
    const int w    = (blockIdx.x * blockDim.x + threadIdx.x) >> 5;
    const int lane = threadIdx.x & 31;
    const int h = w & 15;
    const int l = (w >> 4) & (Lc - 1);
    const int b = w >> 16;

    const size_t tok   = (size_t)(b * Lc + l);
    const size_t qbase = tok * NQK + h * HD + lane * 2;          // q cols
    const size_t kbase = qbase + HID;                            // k cols
    const size_t obase = tok * HID + h * HD + lane * 2;
    const size_t gbase = (size_t)b * HID + h * HD + lane * 2;

    float2 qv = *(const float2*)(qk + qbase);
    float2 k0 = *(const float2*)(g_ak + gbase);
    float2 v0 = *(const float2*)(g_av + gbase);
    float2 k1 = make_float2(0.f, 0.f);
    float2 k3 = make_float2(0.f, 0.f);
    if (l > 0)      k1 = *(const float2*)(qk + kbase - NQK);
    float2 k2 = *(const float2*)(qk + kbase);
    if (l < Lc - 1) k3 = *(const float2*)(qk + kbase + NQK);

    float p0 = qv.x * k0.x + qv.y * k0.y;
    float p1 = qv.x * k1.x + qv.y * k1.y;
    float p2 = qv.x * k2.x + qv.y * k2.y;
    float p3 = qv.x * k3.x + qv.y * k3.y;
    #pragma unroll
    for (int o = 16; o; o >>= 1) {
        p0 += __shfl_xor_sync(0xFFFFFFFFu, p0, o);
        p1 += __shfl_xor_sync(0xFFFFFFFFu, p1, o);
        p2 += __shfl_xor_sync(0xFFFFFFFFu, p2, o);
        p3 += __shfl_xor_sync(0xFFFFFFFFu, p3, o);
    }
    const float scale = 0.125f;
    float s0 = p0 * scale, s1 = p1 * scale, s2 = p2 * scale, s3 = p3 * scale;
    float m = fmaxf(fmaxf(s0, s1), fmaxf(s2, s3));
    float e0 = __expf(s0 - m), e1 = __expf(s1 - m),
          e2 = __expf(s2 - m), e3 = __expf(s3 - m);
    float inv = 1.f / (e0 + e1 + e2 + e3);
    float a0 = e0 * inv, a1 = e1 * inv, a2 = e2 * inv, a3 = e3 * inv;

    float ox = a0 * v0.x + a1 * k1.x + a2 * k2.x + a3 * k3.x;
    float oy = a0 * v0.y + a1 * k1.y + a2 * k2.y + a3 * k3.y;

    *(__half2*)(ahi + obase) = __half2(__float2half_rn(ox), __float2half_rn(oy));
}

// ---------------------------------------------------------------------------
extern "C" void kernel_launch(void* const* d_in, const int* in_sizes, int n_in,
                              void* d_out, int out_size)
{
    const float* x    = (const float*)d_in[0];
    const float* ax   = (const float*)d_in[1];
    const float* WQ_w = (const float*)d_in[2];
    const float* WQ_b = (const float*)d_in[3];
    const float* WK_w = (const float*)d_in[4];
    const float* WK_b = (const float*)d_in[5];
    const float* WV_w = (const float*)d_in[6];
    const float* WV_b = (const float*)d_in[7];
    const float* WO_w = (const float*)d_in[8];
    const float* WO_b = (const float*)d_in[9];
    float* out = (float*)d_out;

    float *qkp, *bqk;
    __half *xhi, *ahi, *wqkh, *wqkl, *woh, *wol;
    cudaGetSymbolAddress((void**)&qkp,  g_qk);
    cudaGetSymbolAddress((void**)&bqk,  g_bqk);
    cudaGetSymbolAddress((void**)&xhi,  g_xhi);
    cudaGetSymbolAddress((void**)&ahi,  g_ahi);
    cudaGetSymbolAddress((void**)&wqkh, g_wqkT_hi);
    cudaGetSymbolAddress((void**)&wqkl, g_wqkT_lo);
    cudaGetSymbolAddress((void**)&woh,  g_woT_hi);
    cudaGetSymbolAddress((void**)&wol,  g_woT_lo);

    cudaFuncSetAttribute(gemm_mma2,
                         cudaFuncAttributeMaxDynamicSharedMemorySize, SMEM_REQ);

    // conversions
    const int n4 = MTOK * HID / 4;
    to_half<<<n4 / 256, 256>>>(x, xhi, n4);
    dim3 tb(32, 8), tg(32, 32);
    transpose_split<<<tg, tb>>>(WQ_w, wqkh, wqkl);                     // rows 0..1023
    transpose_split<<<tg, tb>>>(WK_w, wqkh + (size_t)HID * Kdim,
                                      wqkl + (size_t)HID * Kdim);      // rows 1024..2047
    transpose_split<<<tg, tb>>>(WO_w, woh, wol);
    cudaMemcpyAsync(bqk,       WQ_b, HID * sizeof(float), cudaMemcpyDeviceToDevice);
    cudaMemcpyAsync(bqk + HID, WK_b, HID * sizeof(float), cudaMemcpyDeviceToDevice);
    proj_small<<<64, 256>>>(ax, WK_w, WK_b, WV_w, WV_b);

    // fused Q|K projection: [MTOK, 2048]
    dim3 gqk(NQK / BN, MTOK / BM);   // (16, 256)
    gemm_mma2<<<gqk, 256, SMEM_REQ>>>(xhi, wqkh, wqkl, bqk, qkp, NQK);

    // attention -> fp16 output
    attn_kernel<<<(Bc * Lc * NH) / 8, 256>>>(qkp, ahi);

    // output projection
    dim3 go(HID / BN, MTOK / BM);    // (8, 256)
    gemm_mma2<<<go, 256, SMEM_REQ>>>(ahi, woh, wol, WO_b, out, HID);
}

// round 7
// speedup vs baseline: 1.5799x; 1.5799x over previous
#include <cuda_runtime.h>
#include <cuda_fp16.h>

// ---------------------------------------------------------------------------
// Problem constants
// ---------------------------------------------------------------------------
constexpr int Bc  = 8;
constexpr int Lc  = 4096;
constexpr int NH  = 16;
constexpr int HD  = 64;
constexpr int HID = 1024;
constexpr int MTOK = Bc * Lc;       // 32768
constexpr int Kdim = 1024;
constexpr int NQK  = 2048;          // fused Q|K output width

// GEMM tiling: CTA 256x128, BK=64, 512 threads (16 warps, 4x4), warp 64x32
constexpr int BM = 256, BN = 128, BK = 64;
constexpr int NC = Kdim / BK;       // 16 k-chunks
// stage layout (bytes): A 32K | Bhi 16K | Blo 16K
constexpr int ST_A   = 0;
constexpr int ST_BHI = 32768;
constexpr int ST_BLO = 49152;
constexpr int STAGE_BYTES = 65536;
constexpr int NSLOT = 3;
constexpr int SMEM_REQ = NSLOT * STAGE_BYTES + 1024;

// ---------------------------------------------------------------------------
// Scratch (device globals: no allocation allowed)
// ---------------------------------------------------------------------------
__device__ float g_qk [(size_t)MTOK * NQK];    // fused Q|K output (fp32)
__device__ float g_ak [Bc * HID];
__device__ float g_av [Bc * HID];
__device__ float g_bqk[NQK];                   // concat bias
__device__ __half g_xhi [(size_t)MTOK * HID];
__device__ __half g_ahi [(size_t)MTOK * HID];  // attention out (fp16 hi)
__device__ __half g_wqkT_hi[(size_t)NQK * Kdim], g_wqkT_lo[(size_t)NQK * Kdim];
__device__ __half g_woT_hi [(size_t)Kdim * HID], g_woT_lo [(size_t)Kdim * HID];

// ---------------------------------------------------------------------------
// helpers
// ---------------------------------------------------------------------------
__device__ __forceinline__ unsigned smem_u32(const void* p) {
    unsigned a;
    asm("{ .reg .u64 t; cvta.to.shared.u64 t, %1; cvt.u32.u64 %0, t; }"
        : "=r"(a) : "l"(p));
    return a;
}
__device__ __forceinline__ void cp16(unsigned saddr, const void* g) {
    asm volatile("cp.async.cg.shared.global [%0], [%1], 16;\n"
                 :: "r"(saddr), "l"(g));
}
#define CP_COMMIT() asm volatile("cp.async.commit_group;\n" ::: "memory")
#define CP_WAIT1()  asm volatile("cp.async.wait_group 1;\n" ::: "memory")
#define CP_WAIT0()  asm volatile("cp.async.wait_group 0;\n" ::: "memory")

__device__ __forceinline__ void ldsm4(unsigned& r0, unsigned& r1,
                                      unsigned& r2, unsigned& r3, unsigned a) {
    asm volatile("ldmatrix.sync.aligned.m8n8.x4.shared.b16 {%0,%1,%2,%3}, [%4];"
                 : "=r"(r0), "=r"(r1), "=r"(r2), "=r"(r3) : "r"(a));
}
__device__ __forceinline__ void mma16816(float* c, const unsigned* a,
                                         const unsigned* b) {
    asm volatile(
        "mma.sync.aligned.m16n8k16.row.col.f32.f16.f16.f32 "
        "{%0,%1,%2,%3}, {%4,%5,%6,%7}, {%8,%9}, {%0,%1,%2,%3};"
        : "+f"(c[0]), "+f"(c[1]), "+f"(c[2]), "+f"(c[3])
        : "r"(a[0]), "r"(a[1]), "r"(a[2]), "r"(a[3]), "r"(b[0]), "r"(b[1]));
}

// ---------------------------------------------------------------------------
// 2-pass split-fp16 HMMA GEMM: C[M, N] = Ahi @ (Bhi + Blo)^T + bias
// B operands transposed: [N, K] K-major. CTA 256x128, BK=64, 16 warps (4x4),
// warp tile 64x32, 3-slot cp.async pipeline (R5-proven: wait -> sync -> load),
// exact tail invariant via empty commit groups.
// At top of iter c: commits issued = 2 + c; wait_group 1 => >= c+1 retired
// => chunk c landed. sync after wait gives cross-thread visibility.
// ---------------------------------------------------------------------------
__global__ __launch_bounds__(512, 1)
void gemm_mma2(const __half* __restrict__ Ahi,
               const __half* __restrict__ Bhi, const __half* __restrict__ Blo,
               const float* __restrict__ bias, float* __restrict__ C, int ldc)
{
    extern __shared__ char smem_raw[];
    const unsigned sbase = (smem_u32(smem_raw) + 1023u) & ~1023u;
    const int tid  = threadIdx.x;
    const int wid  = tid >> 5;
    const int lane = tid & 31;
    const int row0 = blockIdx.y * BM;
    const int col0 = blockIdx.x * BN;

    auto load_chunk = [&](int c, int slot) {
        const unsigned sa = sbase + slot * STAGE_BYTES;
        const int kt = c * BK;
        #pragma unroll
        for (int i = 0; i < 4; ++i) {                 // A: 2048 x 16B
            int v = tid + i * 512;
            int r = v >> 3, u = v & 7;                // row 0..255
            unsigned bo = (unsigned)(r * 128 + u * 16);
            unsigned so = bo ^ ((bo >> 3) & 0x70);    // SW128
            cp16(sa + ST_A + so, Ahi + (size_t)(row0 + r) * Kdim + kt + u * 8);
        }
        #pragma unroll
        for (int i = 0; i < 2; ++i) {                 // B hi+lo: 1024 x 16B each
            int v = tid + i * 512;
            int r = v >> 3, u = v & 7;                // row 0..127
            unsigned bo = (unsigned)(r * 128 + u * 16);
            unsigned so = bo ^ ((bo >> 3) & 0x70);
            size_t go = (size_t)(col0 + r) * Kdim + kt + u * 8;
            cp16(sa + ST_BHI + so, Bhi + go);
            cp16(sa + ST_BLO + so, Blo + go);
        }
        CP_COMMIT();
    };

    // per-lane ldmatrix address components
    const int mrow0 = (wid >> 2) * 64;      // warp M offset (0..192)
    const int nrow0 = (wid & 3) * 32;       // warp N offset (0..96)
    const unsigned rtA  = (lane & 7) + ((lane >> 3) & 1) * 8;
    const unsigned s16A = ((lane >> 4) & 1) * 16;
    const unsigned rtB  = (lane & 7) + ((lane >> 4) & 1) * 8;
    const unsigned s16B = ((lane >> 3) & 1) * 16;
    const unsigned xorv = (lane & 7) * 16;

    float acc[4][4][4];
    #pragma unroll
    for (int mi = 0; mi < 4; ++mi)
        #pragma unroll
        for (int ni = 0; ni < 4; ++ni)
            #pragma unroll
            for (int r = 0; r < 4; ++r) acc[mi][ni][r] = 0.f;

    load_chunk(0, 0);
    load_chunk(1, 1);

    for (int c = 0; c < NC; ++c) {
        const int slot = c % NSLOT;
        CP_WAIT1();                      // own groups: chunk c landed
        __syncthreads();                 // all threads waited -> visible; slot free
        if (c + 2 < NC) load_chunk(c + 2, (c + 2) % NSLOT);
        else            CP_COMMIT();     // empty group keeps invariant exact

        const unsigned sa   = sbase + slot * STAGE_BYTES;
        const unsigned pA   = sa + ST_A   + (mrow0 + rtA) * 128;
        const unsigned pBhi = sa + ST_BHI + (nrow0 + rtB) * 128;
        const unsigned pBlo = sa + ST_BLO + (nrow0 + rtB) * 128;

        #pragma unroll
        for (int kk = 0; kk < 4; ++kk) {
            const unsigned colA = ((unsigned)(kk * 32) + s16A) ^ xorv;
            const unsigned colB = ((unsigned)(kk * 32) + s16B) ^ xorv;
            unsigned ah[4][4], bh[2][4], bl[2][4];
            #pragma unroll
            for (int mi = 0; mi < 4; ++mi)
                ldsm4(ah[mi][0], ah[mi][1], ah[mi][2], ah[mi][3],
                      pA + mi * 2048 + colA);
            #pragma unroll
            for (int nb = 0; nb < 2; ++nb) {
                ldsm4(bh[nb][0], bh[nb][1], bh[nb][2], bh[nb][3],
                      pBhi + nb * 2048 + colB);
                ldsm4(bl[nb][0], bl[nb][1], bl[nb][2], bl[nb][3],
                      pBlo + nb * 2048 + colB);
            }
            #pragma unroll
            for (int mi = 0; mi < 4; ++mi)
                #pragma unroll
                for (int ni = 0; ni < 4; ++ni) {
                    const unsigned* bhp = &bh[ni >> 1][(ni & 1) * 2];
                    const unsigned* blp = &bl[ni >> 1][(ni & 1) * 2];
                    mma16816(acc[mi][ni], ah[mi], bhp);   // A*Bhi
                    mma16816(acc[mi][ni], ah[mi], blp);   // A*Blo
                }
        }
    }
    CP_WAIT0();

    // epilogue: acc + bias -> C
    #pragma unroll
    for (int ni = 0; ni < 4; ++ni) {
        const int cc = col0 + nrow0 + ni * 8 + (lane & 3) * 2;
        const float b0 = bias[cc], b1 = bias[cc + 1];
        #pragma unroll
        for (int mi = 0; mi < 4; ++mi) {
            const int r = row0 + mrow0 + mi * 16 + (lane >> 2);
            float2 v0 = make_float2(acc[mi][ni][0] + b0, acc[mi][ni][1] + b1);
            float2 v1 = make_float2(acc[mi][ni][2] + b0, acc[mi][ni][3] + b1);
            *(float2*)(C + (size_t)r * ldc + cc)       = v0;
            *(float2*)(C + (size_t)(r + 8) * ldc + cc) = v1;
        }
    }
}

// ---------------------------------------------------------------------------
// fp32 -> fp16 convert (hi only), vectorized
// ---------------------------------------------------------------------------
__global__ __launch_bounds__(256)
void to_half(const float* __restrict__ in, __half* __restrict__ out, int n4)
{
    int i = blockIdx.x * blockDim.x + threadIdx.x;
    if (i >= n4) return;
    float4 v = ((const float4*)in)[i];
    __half2* op = (__half2*)(out + (size_t)i * 4);
    op[0] = __half2(__float2half_rn(v.x), __float2half_rn(v.y));
    op[1] = __half2(__float2half_rn(v.z), __float2half_rn(v.w));
}

// ---------------------------------------------------------------------------
// Batched: W [K,N] fp32 -> W^T hi/lo fp16 [N,K], 3 weights in one launch (z)
// ---------------------------------------------------------------------------
__global__ __launch_bounds__(256)
void transpose_split3(const float* __restrict__ W0, __half* __restrict__ H0, __half* __restrict__ L0,
                      const float* __restrict__ W1, __half* __restrict__ H1, __half* __restrict__ L1,
                      const float* __restrict__ W2, __half* __restrict__ H2, __half* __restrict__ L2)
{
    const float* W; __half *Th, *Tl;
    if      (blockIdx.z == 0) { W = W0; Th = H0; Tl = L0; }
    else if (blockIdx.z == 1) { W = W1; Th = H1; Tl = L1; }
    else                      { W = W2; Th = H2; Tl = L2; }

    __shared__ float t[32][33];
    const int tx = threadIdx.x, ty = threadIdx.y;   // (32, 8)
    const int n0 = blockIdx.x * 32, k0 = blockIdx.y * 32;
    #pragma unroll
    for (int i = 0; i < 32; i += 8)
        t[ty + i][tx] = W[(size_t)(k0 + ty + i) * HID + n0 + tx];
    __syncthreads();
    #pragma unroll
    for (int i = 0; i < 32; i += 8) {
        float v = t[tx][ty + i];
        __half h = __float2half_rn(v);
        __half l = __float2half_rn(v - __half2float(h));
        Th[(size_t)(n0 + ty + i) * Kdim + k0 + tx] = h;
        Tl[(size_t)(n0 + ty + i) * Kdim + k0 + tx] = l;
    }
}

// ---------------------------------------------------------------------------
// Tiny projections: ak = ax@WK + bK, av = ax@WV + bV (fp32, 8x1024 each)
// ---------------------------------------------------------------------------
__global__ __launch_bounds__(256)
void proj_small(const float* __restrict__ ax,
                const float* __restrict__ WK, const float* __restrict__ WKb,
                const float* __restrict__ WV, const float* __restrict__ WVb)
{
    __shared__ float xs[HID];
    const int sel = blockIdx.x >> 5;
    const int bb  = (blockIdx.x >> 2) & 7;
    const int n   = ((blockIdx.x & 3) << 8) + threadIdx.x;
    for (int i = threadIdx.x; i < HID; i += 256) xs[i] = ax[bb * HID + i];
    __syncthreads();
    const float* W    = sel ? WV  : WK;
    const float* bias = sel ? WVb : WKb;
    float acc = 0.f;
    #pragma unroll 8
    for (int kk = 0; kk < HID; ++kk)
        acc = fmaf(xs[kk], W[(size_t)kk * HID + n], acc);
    float* o = sel ? g_av : g_ak;
    o[bb * HID + n] = acc + bias[n];
}

// ---------------------------------------------------------------------------
// Attention on fused qk buffer (row stride NQK), emits fp16 output.
// ---------------------------------------------------------------------------
__global__ __launch_bounds__(256)
void attn_kernel(const float* __restrict__ qk, __half* __restrict__ ahi)
{
    const int w    = (blockIdx.x * blockDim.x + threadIdx.x) >> 5;
    const int lane = threadIdx.x & 31;
    const int h = w & 15;
    const int l = (w >> 4) & (Lc - 1);
    const int b = w >> 16;

    const size_t tok   = (size_t)(b * Lc + l);
    const size_t qbase = tok * NQK + h * HD + lane * 2;          // q cols
    const size_t kbase = qbase + HID;                            // k cols
    const size_t obase = tok * HID + h * HD + lane * 2;
    const size_t gbase = (size_t)b * HID + h * HD + lane * 2;

    float2 qv = *(const float2*)(qk + qbase);
    float2 k0 = *(const float2*)(g_ak + gbase);
    float2 v0 = *(const float2*)(g_av + gbase);
    float2 k1 = make_float2(0.f, 0.f);
    float2 k3 = make_float2(0.f, 0.f);
    if (l > 0)      k1 = *(const float2*)(qk + kbase - NQK);
    float2 k2 = *(const float2*)(qk + kbase);
    if (l < Lc - 1) k3 = *(const float2*)(qk + kbase + NQK);

    float p0 = qv.x * k0.x + qv.y * k0.y;
    float p1 = qv.x * k1.x + qv.y * k1.y;
    float p2 = qv.x * k2.x + qv.y * k2.y;
    float p3 = qv.x * k3.x + qv.y * k3.y;
    #pragma unroll
    for (int o = 16; o; o >>= 1) {
        p0 += __shfl_xor_sync(0xFFFFFFFFu, p0, o);
        p1 += __shfl_xor_sync(0xFFFFFFFFu, p1, o);
        p2 += __shfl_xor_sync(0xFFFFFFFFu, p2, o);
        p3 += __shfl_xor_sync(0xFFFFFFFFu, p3, o);
    }
    const float scale = 0.125f;
    float s0 = p0 * scale, s1 = p1 * scale, s2 = p2 * scale, s3 = p3 * scale;
    float m = fmaxf(fmaxf(s0, s1), fmaxf(s2, s3));
    float e0 = __expf(s0 - m), e1 = __expf(s1 - m),
          e2 = __expf(s2 - m), e3 = __expf(s3 - m);
    float inv = 1.f / (e0 + e1 + e2 + e3);
    float a0 = e0 * inv, a1 = e1 * inv, a2 = e2 * inv, a3 = e3 * inv;

    float ox = a0 * v0.x + a1 * k1.x + a2 * k2.x + a3 * k3.x;
    float oy = a0 * v0.y + a1 * k1.y + a2 * k2.y + a3 * k3.y;

    *(__half2*)(ahi + obase) = __half2(__float2half_rn(ox), __float2half_rn(oy));
}

// ---------------------------------------------------------------------------
extern "C" void kernel_launch(void* const* d_in, const int* in_sizes, int n_in,
                              void* d_out, int out_size)
{
    const float* x    = (const float*)d_in[0];
    const float* ax   = (const float*)d_in[1];
    const float* WQ_w = (const float*)d_in[2];
    const float* WQ_b = (const float*)d_in[3];
    const float* WK_w = (const float*)d_in[4];
    const float* WK_b = (const float*)d_in[5];
    const float* WV_w = (const float*)d_in[6];
    const float* WV_b = (const float*)d_in[7];
    const float* WO_w = (const float*)d_in[8];
    const float* WO_b = (const float*)d_in[9];
    float* out = (float*)d_out;

    float *qkp, *bqk;
    __half *xhi, *ahi, *wqkh, *wqkl, *woh, *wol;
    cudaGetSymbolAddress((void**)&qkp,  g_qk);
    cudaGetSymbolAddress((void**)&bqk,  g_bqk);
    cudaGetSymbolAddress((void**)&xhi,  g_xhi);
    cudaGetSymbolAddress((void**)&ahi,  g_ahi);
    cudaGetSymbolAddress((void**)&wqkh, g_wqkT_hi);
    cudaGetSymbolAddress((void**)&wqkl, g_wqkT_lo);
    cudaGetSymbolAddress((void**)&woh,  g_woT_hi);
    cudaGetSymbolAddress((void**)&wol,  g_woT_lo);

    cudaFuncSetAttribute(gemm_mma2,
                         cudaFuncAttributeMaxDynamicSharedMemorySize, SMEM_REQ);

    // conversions
    const int n4 = MTOK * HID / 4;
    to_half<<<n4 / 256, 256>>>(x, xhi, n4);
    dim3 tb(32, 8), tg(32, 32, 3);
    transpose_split3<<<tg, tb>>>(
        WQ_w, wqkh,                       wqkl,
        WK_w, wqkh + (size_t)HID * Kdim,  wqkl + (size_t)HID * Kdim,
        WO_w, woh,                        wol);
    cudaMemcpyAsync(bqk,       WQ_b, HID * sizeof(float), cudaMemcpyDeviceToDevice);
    cudaMemcpyAsync(bqk + HID, WK_b, HID * sizeof(float), cudaMemcpyDeviceToDevice);
    proj_small<<<64, 256>>>(ax, WK_w, WK_b, WV_w, WV_b);

    // fused Q|K projection: [MTOK, 2048]
    dim3 gqk(NQK / BN, MTOK / BM);   // (16, 128)
    gemm_mma2<<<gqk, 512, SMEM_REQ>>>(xhi, wqkh, wqkl, bqk, qkp, NQK);

    // attention -> fp16 output
    attn_kernel<<<(Bc * Lc * NH) / 8, 256>>>(qkp, ahi);

    // output projection
    dim3 go(HID / BN, MTOK / BM);    // (8, 128)
    gemm_mma2<<<go, 512, SMEM_REQ>>>(ahi, woh, wol, WO_b, out, HID);
}

// round 8
// speedup vs baseline: 1.5867x; 1.0043x over previous
#include <cuda_runtime.h>
#include <cuda_fp16.h>

// ---------------------------------------------------------------------------
// Problem constants
// ---------------------------------------------------------------------------
constexpr int Bc  = 8;
constexpr int Lc  = 4096;
constexpr int NH  = 16;
constexpr int HD  = 64;
constexpr int HID = 1024;
constexpr int MTOK = Bc * Lc;       // 32768
constexpr int Kdim = 1024;
constexpr int NQK  = 2048;          // fused Q|K output width

// GEMM tiling: CTA 256x128, BK=64, 512 threads (16 warps, 4x4), warp 64x32
constexpr int BM = 256, BN = 128, BK = 64;
constexpr int NC = Kdim / BK;       // 16 k-chunks
// stage layout (bytes): A 32K | Bhi 16K | Blo 16K
constexpr int ST_A   = 0;
constexpr int ST_BHI = 32768;
constexpr int ST_BLO = 49152;
constexpr int STAGE_BYTES = 65536;
constexpr int NSLOT = 3;
constexpr int SMEM_REQ = NSLOT * STAGE_BYTES + 1024;

// ---------------------------------------------------------------------------
// Scratch (device globals: no allocation allowed)
// ---------------------------------------------------------------------------
__device__ __half g_qk [(size_t)MTOK * NQK];   // fused Q|K output (fp16)
__device__ float g_ak [Bc * HID];
__device__ float g_av [Bc * HID];
__device__ float g_bqk[NQK];                   // concat bias
__device__ __half g_xhi [(size_t)MTOK * HID];
__device__ __half g_ahi [(size_t)MTOK * HID];  // attention out (fp16 hi)
__device__ __half g_wqkT_hi[(size_t)NQK * Kdim], g_wqkT_lo[(size_t)NQK * Kdim];
__device__ __half g_woT_hi [(size_t)Kdim * HID], g_woT_lo [(size_t)Kdim * HID];

// ---------------------------------------------------------------------------
// helpers
// ---------------------------------------------------------------------------
__device__ __forceinline__ unsigned smem_u32(const void* p) {
    unsigned a;
    asm("{ .reg .u64 t; cvta.to.shared.u64 t, %1; cvt.u32.u64 %0, t; }"
        : "=r"(a) : "l"(p));
    return a;
}
__device__ __forceinline__ void cp16(unsigned saddr, const void* g) {
    asm volatile("cp.async.cg.shared.global [%0], [%1], 16;\n"
                 :: "r"(saddr), "l"(g));
}
#define CP_COMMIT() asm volatile("cp.async.commit_group;\n" ::: "memory")
#define CP_WAIT1()  asm volatile("cp.async.wait_group 1;\n" ::: "memory")
#define CP_WAIT0()  asm volatile("cp.async.wait_group 0;\n" ::: "memory")

__device__ __forceinline__ void ldsm4(unsigned& r0, unsigned& r1,
                                      unsigned& r2, unsigned& r3, unsigned a) {
    asm volatile("ldmatrix.sync.aligned.m8n8.x4.shared.b16 {%0,%1,%2,%3}, [%4];"
                 : "=r"(r0), "=r"(r1), "=r"(r2), "=r"(r3) : "r"(a));
}
__device__ __forceinline__ void mma16816(float* c, const unsigned* a,
                                         const unsigned* b) {
    asm volatile(
        "mma.sync.aligned.m16n8k16.row.col.f32.f16.f16.f32 "
        "{%0,%1,%2,%3}, {%4,%5,%6,%7}, {%8,%9}, {%0,%1,%2,%3};"
        : "+f"(c[0]), "+f"(c[1]), "+f"(c[2]), "+f"(c[3])
        : "r"(a[0]), "r"(a[1]), "r"(a[2]), "r"(a[3]), "r"(b[0]), "r"(b[1]));
}

// ---------------------------------------------------------------------------
// 2-pass split-fp16 HMMA GEMM: C[M, N] = Ahi @ (Bhi + Blo)^T + bias
// B operands transposed: [N, K] K-major. CTA 256x128, BK=64, 16 warps (4x4),
// warp tile 64x32, 3-slot cp.async pipeline (proven: wait -> sync -> load),
// exact tail invariant via empty commit groups.
// HOUT: write fp16 output (qk buffer) vs fp32 (final out).
// ---------------------------------------------------------------------------
template <bool HOUT>
__global__ __launch_bounds__(512, 1)
void gemm_mma2(const __half* __restrict__ Ahi,
               const __half* __restrict__ Bhi, const __half* __restrict__ Blo,
               const float* __restrict__ bias, void* __restrict__ Cout, int ldc)
{
    extern __shared__ char smem_raw[];
    const unsigned sbase = (smem_u32(smem_raw) + 1023u) & ~1023u;
    const int tid  = threadIdx.x;
    const int wid  = tid >> 5;
    const int lane = tid & 31;
    const int row0 = blockIdx.y * BM;
    const int col0 = blockIdx.x * BN;

    auto load_chunk = [&](int c, int slot) {
        const unsigned sa = sbase + slot * STAGE_BYTES;
        const int kt = c * BK;
        #pragma unroll
        for (int i = 0; i < 4; ++i) {                 // A: 2048 x 16B
            int v = tid + i * 512;
            int r = v >> 3, u = v & 7;                // row 0..255
            unsigned bo = (unsigned)(r * 128 + u * 16);
            unsigned so = bo ^ ((bo >> 3) & 0x70);    // SW128
            cp16(sa + ST_A + so, Ahi + (size_t)(row0 + r) * Kdim + kt + u * 8);
        }
        #pragma unroll
        for (int i = 0; i < 2; ++i) {                 // B hi+lo: 1024 x 16B each
            int v = tid + i * 512;
            int r = v >> 3, u = v & 7;                // row 0..127
            unsigned bo = (unsigned)(r * 128 + u * 16);
            unsigned so = bo ^ ((bo >> 3) & 0x70);
            size_t go = (size_t)(col0 + r) * Kdim + kt + u * 8;
            cp16(sa + ST_BHI + so, Bhi + go);
            cp16(sa + ST_BLO + so, Blo + go);
        }
        CP_COMMIT();
    };

    // per-lane ldmatrix address components
    const int mrow0 = (wid >> 2) * 64;      // warp M offset (0..192)
    const int nrow0 = (wid & 3) * 32;       // warp N offset (0..96)
    const unsigned rtA  = (lane & 7) + ((lane >> 3) & 1) * 8;
    const unsigned s16A = ((lane >> 4) & 1) * 16;
    const unsigned rtB  = (lane & 7) + ((lane >> 4) & 1) * 8;
    const unsigned s16B = ((lane >> 3) & 1) * 16;
    const unsigned xorv = (lane & 7) * 16;

    float acc[4][4][4];
    #pragma unroll
    for (int mi = 0; mi < 4; ++mi)
        #pragma unroll
        for (int ni = 0; ni < 4; ++ni)
            #pragma unroll
            for (int r = 0; r < 4; ++r) acc[mi][ni][r] = 0.f;

    load_chunk(0, 0);
    load_chunk(1, 1);

    for (int c = 0; c < NC; ++c) {
        const int slot = c % NSLOT;
        CP_WAIT1();                      // chunk c landed (this thread's part)
        __syncthreads();                 // cross-thread visibility; slot free
        if (c + 2 < NC) load_chunk(c + 2, (c + 2) % NSLOT);
        else            CP_COMMIT();     // empty group keeps invariant exact

        const unsigned sa   = sbase + slot * STAGE_BYTES;
        const unsigned pA   = sa + ST_A   + (mrow0 + rtA) * 128;
        const unsigned pBhi = sa + ST_BHI + (nrow0 + rtB) * 128;
        const unsigned pBlo = sa + ST_BLO + (nrow0 + rtB) * 128;

        #pragma unroll
        for (int kk = 0; kk < 4; ++kk) {
            const unsigned colA = ((unsigned)(kk * 32) + s16A) ^ xorv;
            const unsigned colB = ((unsigned)(kk * 32) + s16B) ^ xorv;
            unsigned ah[4][4], bh[2][4], bl[2][4];
            #pragma unroll
            for (int mi = 0; mi < 4; ++mi)
                ldsm4(ah[mi][0], ah[mi][1], ah[mi][2], ah[mi][3],
                      pA + mi * 2048 + colA);
            #pragma unroll
            for (int nb = 0; nb < 2; ++nb) {
                ldsm4(bh[nb][0], bh[nb][1], bh[nb][2], bh[nb][3],
                      pBhi + nb * 2048 + colB);
                ldsm4(bl[nb][0], bl[nb][1], bl[nb][2], bl[nb][3],
                      pBlo + nb * 2048 + colB);
            }
            #pragma unroll
            for (int mi = 0; mi < 4; ++mi)
                #pragma unroll
                for (int ni = 0; ni < 4; ++ni) {
                    const unsigned* bhp = &bh[ni >> 1][(ni & 1) * 2];
                    const unsigned* blp = &bl[ni >> 1][(ni & 1) * 2];
                    mma16816(acc[mi][ni], ah[mi], bhp);   // A*Bhi
                    mma16816(acc[mi][ni], ah[mi], blp);   // A*Blo
                }
        }
    }
    CP_WAIT0();

    // epilogue: acc + bias -> C (fp16 or fp32)
    #pragma unroll
    for (int ni = 0; ni < 4; ++ni) {
        const int cc = col0 + nrow0 + ni * 8 + (lane & 3) * 2;
        const float b0 = bias[cc], b1 = bias[cc + 1];
        #pragma unroll
        for (int mi = 0; mi < 4; ++mi) {
            const int r = row0 + mrow0 + mi * 16 + (lane >> 2);
            if (HOUT) {
                __half* C = (__half*)Cout;
                *(__half2*)(C + (size_t)r * ldc + cc) =
                    __half2(__float2half_rn(acc[mi][ni][0] + b0),
                            __float2half_rn(acc[mi][ni][1] + b1));
                *(__half2*)(C + (size_t)(r + 8) * ldc + cc) =
                    __half2(__float2half_rn(acc[mi][ni][2] + b0),
                            __float2half_rn(acc[mi][ni][3] + b1));
            } else {
                float* C = (float*)Cout;
                *(float2*)(C + (size_t)r * ldc + cc) =
                    make_float2(acc[mi][ni][0] + b0, acc[mi][ni][1] + b1);
                *(float2*)(C + (size_t)(r + 8) * ldc + cc) =
                    make_float2(acc[mi][ni][2] + b0, acc[mi][ni][3] + b1);
            }
        }
    }
}

// ---------------------------------------------------------------------------
// fp32 -> fp16 convert (hi only), vectorized
// ---------------------------------------------------------------------------
__global__ __launch_bounds__(256)
void to_half(const float* __restrict__ in, __half* __restrict__ out, int n4)
{
    int i = blockIdx.x * blockDim.x + threadIdx.x;
    if (i >= n4) return;
    float4 v = ((const float4*)in)[i];
    __half2* op = (__half2*)(out + (size_t)i * 4);
    op[0] = __half2(__float2half_rn(v.x), __float2half_rn(v.y));
    op[1] = __half2(__float2half_rn(v.z), __float2half_rn(v.w));
}

// ---------------------------------------------------------------------------
// Batched: W [K,N] fp32 -> W^T hi/lo fp16 [N,K], 3 weights in one launch (z)
// ---------------------------------------------------------------------------
__global__ __launch_bounds__(256)
void transpose_split3(const float* __restrict__ W0, __half* __restrict__ H0, __half* __restrict__ L0,
                      const float* __restrict__ W1, __half* __restrict__ H1, __half* __restrict__ L1,
                      const float* __restrict__ W2, __half* __restrict__ H2, __half* __restrict__ L2)
{
    const float* W; __half *Th, *Tl;
    if      (blockIdx.z == 0) { W = W0; Th = H0; Tl = L0; }
    else if (blockIdx.z == 1) { W = W1; Th = H1; Tl = L1; }
    else                      { W = W2; Th = H2; Tl = L2; }

    __shared__ float t[32][33];
    const int tx = threadIdx.x, ty = threadIdx.y;   // (32, 8)
    const int n0 = blockIdx.x * 32, k0 = blockIdx.y * 32;
    #pragma unroll
    for (int i = 0; i < 32; i += 8)
        t[ty + i][tx] = W[(size_t)(k0 + ty + i) * HID + n0 + tx];
    __syncthreads();
    #pragma unroll
    for (int i = 0; i < 32; i += 8) {
        float v = t[tx][ty + i];
        __half h = __float2half_rn(v);
        __half l = __float2half_rn(v - __half2float(h));
        Th[(size_t)(n0 + ty + i) * Kdim + k0 + tx] = h;
        Tl[(size_t)(n0 + ty + i) * Kdim + k0 + tx] = l;
    }
}

// ---------------------------------------------------------------------------
// Tiny projections: ak = ax@WK + bK, av = ax@WV + bV (fp32, 8x1024 each)
// ---------------------------------------------------------------------------
__global__ __launch_bounds__(256)
void proj_small(const float* __restrict__ ax,
                const float* __restrict__ WK, const float* __restrict__ WKb,
                const float* __restrict__ WV, const float* __restrict__ WVb)
{
    __shared__ float xs[HID];
    const int sel = blockIdx.x >> 5;
    const int bb  = (blockIdx.x >> 2) & 7;
    const int n   = ((blockIdx.x & 3) << 8) + threadIdx.x;
    for (int i = threadIdx.x; i < HID; i += 256) xs[i] = ax[bb * HID + i];
    __syncthreads();
    const float* W    = sel ? WV  : WK;
    const float* bias = sel ? WVb : WKb;
    float acc = 0.f;
    #pragma unroll 8
    for (int kk = 0; kk < HID; ++kk)
        acc = fmaf(xs[kk], W[(size_t)kk * HID + n], acc);
    float* o = sel ? g_av : g_ak;
    o[bb * HID + n] = acc + bias[n];
}

// ---------------------------------------------------------------------------
// Attention on fused fp16 qk buffer (row stride NQK), emits fp16 output.
// ---------------------------------------------------------------------------
__global__ __launch_bounds__(256)
void attn_kernel(const __half* __restrict__ qk, __half* __restrict__ ahi)
{
    const int w    = (blockIdx.x * blockDim.x + threadIdx.x) >> 5;
    const int lane = threadIdx.x & 31;
    const int h = w & 15;
    const int l = (w >> 4) & (Lc - 1);
    const int b = w >> 16;

    const size_t tok   = (size_t)(b * Lc + l);
    const size_t qbase = tok * NQK + h * HD + lane * 2;          // q cols
    const size_t kbase = qbase + HID;                            // k cols
    const size_t obase = tok * HID + h * HD + lane * 2;
    const size_t gbase = (size_t)b * HID + h * HD + lane * 2;

    float2 qv = __half22float2(*(const __half2*)(qk + qbase));
    float2 k0 = *(const float2*)(g_ak + gbase);
    float2 v0 = *(const float2*)(g_av + gbase);
    float2 k1 = make_float2(0.f, 0.f);
    float2 k3 = make_float2(0.f, 0.f);
    if (l > 0)      k1 = __half22float2(*(const __half2*)(qk + kbase - NQK));
    float2 k2 = __half22float2(*(const __half2*)(qk + kbase));
    if (l < Lc - 1) k3 = __half22float2(*(const __half2*)(qk + kbase + NQK));

    float p0 = qv.x * k0.x + qv.y * k0.y;
    float p1 = qv.x * k1.x + qv.y * k1.y;
    float p2 = qv.x * k2.x + qv.y * k2.y;
    float p3 = qv.x * k3.x + qv.y * k3.y;
    #pragma unroll
    for (int o = 16; o; o >>= 1) {
        p0 += __shfl_xor_sync(0xFFFFFFFFu, p0, o);
        p1 += __shfl_xor_sync(0xFFFFFFFFu, p1, o);
        p2 += __shfl_xor_sync(0xFFFFFFFFu, p2, o);
        p3 += __shfl_xor_sync(0xFFFFFFFFu, p3, o);
    }
    const float scale = 0.125f;
    float s0 = p0 * scale, s1 = p1 * scale, s2 = p2 * scale, s3 = p3 * scale;
    float m = fmaxf(fmaxf(s0, s1), fmaxf(s2, s3));
    float e0 = __expf(s0 - m), e1 = __expf(s1 - m),
          e2 = __expf(s2 - m), e3 = __expf(s3 - m);
    float inv = 1.f / (e0 + e1 + e2 + e3);
    float a0 = e0 * inv, a1 = e1 * inv, a2 = e2 * inv, a3 = e3 * inv;

    float ox = a0 * v0.x + a1 * k1.x + a2 * k2.x + a3 * k3.x;
    float oy = a0 * v0.y + a1 * k1.y + a2 * k2.y + a3 * k3.y;

    *(__half2*)(ahi + obase) = __half2(__float2half_rn(ox), __float2half_rn(oy));
}

// ---------------------------------------------------------------------------
extern "C" void kernel_launch(void* const* d_in, const int* in_sizes, int n_in,
                              void* d_out, int out_size)
{
    const float* x    = (const float*)d_in[0];
    const float* ax   = (const float*)d_in[1];
    const float* WQ_w = (const float*)d_in[2];
    const float* WQ_b = (const float*)d_in[3];
    const float* WK_w = (const float*)d_in[4];
    const float* WK_b = (const float*)d_in[5];
    const float* WV_w = (const float*)d_in[6];
    const float* WV_b = (const float*)d_in[7];
    const float* WO_w = (const float*)d_in[8];
    const float* WO_b = (const float*)d_in[9];
    float* out = (float*)d_out;

    float* bqk;
    __half *qkp, *xhi, *ahi, *wqkh, *wqkl, *woh, *wol;
    cudaGetSymbolAddress((void**)&qkp,  g_qk);
    cudaGetSymbolAddress((void**)&bqk,  g_bqk);
    cudaGetSymbolAddress((void**)&xhi,  g_xhi);
    cudaGetSymbolAddress((void**)&ahi,  g_ahi);
    cudaGetSymbolAddress((void**)&wqkh, g_wqkT_hi);
    cudaGetSymbolAddress((void**)&wqkl, g_wqkT_lo);
    cudaGetSymbolAddress((void**)&woh,  g_woT_hi);
    cudaGetSymbolAddress((void**)&wol,  g_woT_lo);

    cudaFuncSetAttribute(gemm_mma2<true>,
                         cudaFuncAttributeMaxDynamicSharedMemorySize, SMEM_REQ);
    cudaFuncSetAttribute(gemm_mma2<false>,
                         cudaFuncAttributeMaxDynamicSharedMemorySize, SMEM_REQ);

    // conversions
    const int n4 = MTOK * HID / 4;
    to_half<<<n4 / 256, 256>>>(x, xhi, n4);
    dim3 tb(32, 8), tg(32, 32, 3);
    transpose_split3<<<tg, tb>>>(
        WQ_w, wqkh,                       wqkl,
        WK_w, wqkh + (size_t)HID * Kdim,  wqkl + (size_t)HID * Kdim,
        WO_w, woh,                        wol);
    cudaMemcpyAsync(bqk,       WQ_b, HID * sizeof(float), cudaMemcpyDeviceToDevice);
    cudaMemcpyAsync(bqk + HID, WK_b, HID * sizeof(float), cudaMemcpyDeviceToDevice);
    proj_small<<<64, 256>>>(ax, WK_w, WK_b, WV_w, WV_b);

    // fused Q|K projection: [MTOK, 2048] fp16
    dim3 gqk(NQK / BN, MTOK / BM);   // (16, 128)
    gemm_mma2<true><<<gqk, 512, SMEM_REQ>>>(xhi, wqkh, wqkl, bqk, qkp, NQK);

    // attention -> fp16 output
    attn_kernel<<<(Bc * Lc * NH) / 8, 256>>>(qkp, ahi);

    // output projection (fp32 out)
    dim3 go(HID / BN, MTOK / BM);    // (8, 128)
    gemm_mma2<false><<<go, 512, SMEM_REQ>>>(ahi, woh, wol, WO_b, out, HID);
}

// round 11
// speedup vs baseline: 2.0377x; 1.2842x over previous
#include <cuda_runtime.h>
#include <cuda_fp16.h>

// ---------------------------------------------------------------------------
// Problem constants
// ---------------------------------------------------------------------------
constexpr int Bc  = 8;
constexpr int Lc  = 4096;
constexpr int NH  = 16;
constexpr int HD  = 64;
constexpr int HID = 1024;
constexpr int MTOK = Bc * Lc;       // 32768
constexpr int Kdim = 1024;
constexpr int NQK  = 2048;          // fused Q|K output width

// GEMM tiling: CTA 256x128, BK=64, 512 threads (16 warps, 4x4), warp 64x32
constexpr int BM = 256, BN = 128, BK = 64;
constexpr int NC = Kdim / BK;       // 16 k-chunks
// stage layout (bytes): A 32K | Bhi 16K | Blo 16K
constexpr int ST_A   = 0;
constexpr int ST_BHI = 32768;
constexpr int ST_BLO = 49152;
constexpr int STAGE_BYTES = 65536;
constexpr int NSLOT = 3;
constexpr int SMEM_REQ = NSLOT * STAGE_BYTES + 1024;

// ---------------------------------------------------------------------------
// Scratch (device globals: no allocation allowed)
// ---------------------------------------------------------------------------
__device__ __half g_qk [(size_t)MTOK * NQK];   // fused Q|K output (fp16)
__device__ float g_ak [Bc * HID];
__device__ float g_av [Bc * HID];
__device__ float g_bqk[NQK];                   // concat bias
__device__ __half g_xhi [(size_t)MTOK * HID];
__device__ __half g_ahi [(size_t)MTOK * HID];  // attention out (fp16 hi)
__device__ __half g_wqkT_hi[(size_t)NQK * Kdim], g_wqkT_lo[(size_t)NQK * Kdim];
__device__ __half g_woT_hi [(size_t)Kdim * HID], g_woT_lo [(size_t)Kdim * HID];

// ---------------------------------------------------------------------------
// helpers
// ---------------------------------------------------------------------------
__device__ __forceinline__ unsigned smem_u32(const void* p) {
    unsigned a;
    asm("{ .reg .u64 t; cvta.to.shared.u64 t, %1; cvt.u32.u64 %0, t; }"
        : "=r"(a) : "l"(p));
    return a;
}
__device__ __forceinline__ void cp16(unsigned saddr, const void* g) {
    asm volatile("cp.async.cg.shared.global [%0], [%1], 16;\n"
                 :: "r"(saddr), "l"(g));
}
#define CP_COMMIT() asm volatile("cp.async.commit_group;\n" ::: "memory")
#define CP_WAIT1()  asm volatile("cp.async.wait_group 1;\n" ::: "memory")
#define CP_WAIT0()  asm volatile("cp.async.wait_group 0;\n" ::: "memory")

__device__ __forceinline__ void ldsm4(unsigned& r0, unsigned& r1,
                                      unsigned& r2, unsigned& r3, unsigned a) {
    asm volatile("ldmatrix.sync.aligned.m8n8.x4.shared.b16 {%0,%1,%2,%3}, [%4];"
                 : "=r"(r0), "=r"(r1), "=r"(r2), "=r"(r3) : "r"(a));
}
__device__ __forceinline__ void mma16816(float* c, const unsigned* a,
                                         const unsigned* b) {
    asm volatile(
        "mma.sync.aligned.m16n8k16.row.col.f32.f16.f16.f32 "
        "{%0,%1,%2,%3}, {%4,%5,%6,%7}, {%8,%9}, {%0,%1,%2,%3};"
        : "+f"(c[0]), "+f"(c[1]), "+f"(c[2]), "+f"(c[3])
        : "r"(a[0]), "r"(a[1]), "r"(a[2]), "r"(a[3]), "r"(b[0]), "r"(b[1]));
}

// ---------------------------------------------------------------------------
// Split-fp16 HMMA GEMM: C[M, N] = Ahi @ (Bhi [+ Blo]) ^T + bias
// B operands transposed: [N, K] K-major. CTA 256x128, BK=64, 16 warps (4x4),
// warp tile 64x32, 3-slot cp.async pipeline (proven: wait -> sync -> load),
// exact tail invariant via empty commit groups.
// HOUT: fp16 output (qk buffer) vs fp32 (final out).
// BLO:  apply the Blo correction pass (2-pass) vs hi-only (1-pass).
// ---------------------------------------------------------------------------
template <bool HOUT, bool BLO>
__global__ __launch_bounds__(512, 1)
void gemm_mma2(const __half* __restrict__ Ahi,
               const __half* __restrict__ Bhi, const __half* __restrict__ Blo,
               const float* __restrict__ bias, void* __restrict__ Cout, int ldc)
{
    extern __shared__ char smem_raw[];
    const unsigned sbase = (smem_u32(smem_raw) + 1023u) & ~1023u;
    const int tid  = threadIdx.x;
    const int wid  = tid >> 5;
    const int lane = tid & 31;
    const int row0 = blockIdx.y * BM;
    const int col0 = blockIdx.x * BN;

    auto load_chunk = [&](int c, int slot) {
        const unsigned sa = sbase + slot * STAGE_BYTES;
        const int kt = c * BK;
        #pragma unroll
        for (int i = 0; i < 4; ++i) {                 // A: 2048 x 16B
            int v = tid + i * 512;
            int r = v >> 3, u = v & 7;                // row 0..255
            unsigned bo = (unsigned)(r * 128 + u * 16);
            unsigned so = bo ^ ((bo >> 3) & 0x70);    // SW128
            cp16(sa + ST_A + so, Ahi + (size_t)(row0 + r) * Kdim + kt + u * 8);
        }
        #pragma unroll
        for (int i = 0; i < 2; ++i) {                 // B hi (+lo): 1024 x 16B each
            int v = tid + i * 512;
            int r = v >> 3, u = v & 7;                // row 0..127
            unsigned bo = (unsigned)(r * 128 + u * 16);
            unsigned so = bo ^ ((bo >> 3) & 0x70);
            size_t go = (size_t)(col0 + r) * Kdim + kt + u * 8;
            cp16(sa + ST_BHI + so, Bhi + go);
            if (BLO) cp16(sa + ST_BLO + so, Blo + go);
        }
        CP_COMMIT();
    };

    // per-lane ldmatrix address components
    const int mrow0 = (wid >> 2) * 64;      // warp M offset (0..192)
    const int nrow0 = (wid & 3) * 32;       // warp N offset (0..96)
    const unsigned rtA  = (lane & 7) + ((lane >> 3) & 1) * 8;
    const unsigned s16A = ((lane >> 4) & 1) * 16;
    const unsigned rtB  = (lane & 7) + ((lane >> 4) & 1) * 8;
    const unsigned s16B = ((lane >> 3) & 1) * 16;
    const unsigned xorv = (lane & 7) * 16;

    float acc[4][4][4];
    #pragma unroll
    for (int mi = 0; mi < 4; ++mi)
        #pragma unroll
        for (int ni = 0; ni < 4; ++ni)
            #pragma unroll
            for (int r = 0; r < 4; ++r) acc[mi][ni][r] = 0.f;

    load_chunk(0, 0);
    load_chunk(1, 1);

    for (int c = 0; c < NC; ++c) {
        const int slot = c % NSLOT;
        CP_WAIT1();                      // chunk c landed (this thread's part)
        __syncthreads();                 // cross-thread visibility; slot free
        if (c + 2 < NC) load_chunk(c + 2, (c + 2) % NSLOT);
        else            CP_COMMIT();     // empty group keeps invariant exact

        const unsigned sa   = sbase + slot * STAGE_BYTES;
        const unsigned pA   = sa + ST_A   + (mrow0 + rtA) * 128;
        const unsigned pBhi = sa + ST_BHI + (nrow0 + rtB) * 128;
        const unsigned pBlo = sa + ST_BLO + (nrow0 + rtB) * 128;

        #pragma unroll
        for (int kk = 0; kk < 4; ++kk) {
            const unsigned colA = ((unsigned)(kk * 32) + s16A) ^ xorv;
            const unsigned colB = ((unsigned)(kk * 32) + s16B) ^ xorv;
            unsigned ah[4][4], bh[2][4], bl[2][4];
            #pragma unroll
            for (int mi = 0; mi < 4; ++mi)
                ldsm4(ah[mi][0], ah[mi][1], ah[mi][2], ah[mi][3],
                      pA + mi * 2048 + colA);
            #pragma unroll
            for (int nb = 0; nb < 2; ++nb) {
                ldsm4(bh[nb][0], bh[nb][1], bh[nb][2], bh[nb][3],
                      pBhi + nb * 2048 + colB);
                if (BLO)
                    ldsm4(bl[nb][0], bl[nb][1], bl[nb][2], bl[nb][3],
                          pBlo + nb * 2048 + colB);
            }
            #pragma unroll
            for (int mi = 0; mi < 4; ++mi)
                #pragma unroll
                for (int ni = 0; ni < 4; ++ni) {
                    const unsigned* bhp = &bh[ni >> 1][(ni & 1) * 2];
                    mma16816(acc[mi][ni], ah[mi], bhp);            // A*Bhi
                    if (BLO) {
                        const unsigned* blp = &bl[ni >> 1][(ni & 1) * 2];
                        mma16816(acc[mi][ni], ah[mi], blp);        // A*Blo
                    }
                }
        }
    }
    CP_WAIT0();

    // epilogue: acc + bias -> C (fp16 or fp32)
    #pragma unroll
    for (int ni = 0; ni < 4; ++ni) {
        const int cc = col0 + nrow0 + ni * 8 + (lane & 3) * 2;
        const float b0 = bias[cc], b1 = bias[cc + 1];
        #pragma unroll
        for (int mi = 0; mi < 4; ++mi) {
            const int r = row0 + mrow0 + mi * 16 + (lane >> 2);
            if (HOUT) {
                __half* C = (__half*)Cout;
                *(__half2*)(C + (size_t)r * ldc + cc) =
                    __half2(__float2half_rn(acc[mi][ni][0] + b0),
                            __float2half_rn(acc[mi][ni][1] + b1));
                *(__half2*)(C + (size_t)(r + 8) * ldc + cc) =
                    __half2(__float2half_rn(acc[mi][ni][2] + b0),
                            __float2half_rn(acc[mi][ni][3] + b1));
            } else {
                float* C = (float*)Cout;
                *(float2*)(C + (size_t)r * ldc + cc) =
                    make_float2(acc[mi][ni][0] + b0, acc[mi][ni][1] + b1);
                *(float2*)(C + (size_t)(r + 8) * ldc + cc) =
                    make_float2(acc[mi][ni][2] + b0, acc[mi][ni][3] + b1);
            }
        }
    }
}

// ---------------------------------------------------------------------------
// fp32 -> fp16 convert (hi only), vectorized
// ---------------------------------------------------------------------------
__global__ __launch_bounds__(256)
void to_half(const float* __restrict__ in, __half* __restrict__ out, int n4)
{
    int i = blockIdx.x * blockDim.x + threadIdx.x;
    if (i >= n4) return;
    float4 v = ((const float4*)in)[i];
    __half2* op = (__half2*)(out + (size_t)i * 4);
    op[0] = __half2(__float2half_rn(v.x), __float2half_rn(v.y));
    op[1] = __half2(__float2half_rn(v.z), __float2half_rn(v.w));
}

// ---------------------------------------------------------------------------
// Batched: W [K,N] fp32 -> W^T hi/lo fp16 [N,K], 3 weights in one launch (z)
// ---------------------------------------------------------------------------
__global__ __launch_bounds__(256)
void transpose_split3(const float* __restrict__ W0, __half* __restrict__ H0, __half* __restrict__ L0,
                      const float* __restrict__ W1, __half* __restrict__ H1, __half* __restrict__ L1,
                      const float* __restrict__ W2, __half* __restrict__ H2, __half* __restrict__ L2)
{
    const float* W; __half *Th, *Tl;
    if      (blockIdx.z == 0) { W = W0; Th = H0; Tl = L0; }
    else if (blockIdx.z == 1) { W = W1; Th = H1; Tl = L1; }
    else                      { W = W2; Th = H2; Tl = L2; }

    __shared__ float t[32][33];
    const int tx = threadIdx.x, ty = threadIdx.y;   // (32, 8)
    const int n0 = blockIdx.x * 32, k0 = blockIdx.y * 32;
    #pragma unroll
    for (int i = 0; i < 32; i += 8)
        t[ty + i][tx] = W[(size_t)(k0 + ty + i) * HID + n0 + tx];
    __syncthreads();
    #pragma unroll
    for (int i = 0; i < 32; i += 8) {
        float v = t[tx][ty + i];
        __half h = __float2half_rn(v);
        __half l = __float2half_rn(v - __half2float(h));
        Th[(size_t)(n0 + ty + i) * Kdim + k0 + tx] = h;
        Tl[(size_t)(n0 + ty + i) * Kdim + k0 + tx] = l;
    }
}

// ---------------------------------------------------------------------------
// Tiny projections: ak = ax@WK + bK, av = ax@WV + bV (fp32, 8x1024 each)
// ---------------------------------------------------------------------------
__global__ __launch_bounds__(256)
void proj_small(const float* __restrict__ ax,
                const float* __restrict__ WK, const float* __restrict__ WKb,
                const float* __restrict__ WV, const float* __restrict__ WVb)
{
    __shared__ float xs[HID];
    const int sel = blockIdx.x >> 5;
    const int bb  = (blockIdx.x >> 2) & 7;
    const int n   = ((blockIdx.x & 3) << 8) + threadIdx.x;
    for (int i = threadIdx.x; i < HID; i += 256) xs[i] = ax[bb * HID + i];
    __syncthreads();
    const float* W    = sel ? WV  : WK;
    const float* bias = sel ? WVb : WKb;
    float acc = 0.f;
    #pragma unroll 8
    for (int kk = 0; kk < HID; ++kk)
        acc = fmaf(xs[kk], W[(size_t)kk * HID + n], acc);
    float* o = sel ? g_av : g_ak;
    o[bb * HID + n] = acc + bias[n];
}

// ---------------------------------------------------------------------------
// Attention on fused fp16 qk buffer (row stride NQK), emits fp16 output.
// ---------------------------------------------------------------------------
__global__ __launch_bounds__(256)
void attn_kernel(const __half* __restrict__ qk, __half* __restrict__ ahi)
{
    const int w    = (blockIdx.x * blockDim.x + threadIdx.x) >> 5;
    const int lane = threadIdx.x & 31;
    const int h = w & 15;
    const int l = (w >> 4) & (Lc - 1);
    const int b = w >> 16;

    const size_t tok   = (size_t)(b * Lc + l);
    const size_t qbase = tok * NQK + h * HD + lane * 2;          // q cols
    const size_t kbase = qbase + HID;                            // k cols
    const size_t obase = tok * HID + h * HD + lane * 2;
    const size_t gbase = (size_t)b * HID + h * HD + lane * 2;

    float2 qv = __half22float2(*(const __half2*)(qk + qbase));
    float2 k0 = *(const float2*)(g_ak + gbase);
    float2 v0 = *(const float2*)(g_av + gbase);
    float2 k1 = make_float2(0.f, 0.f);
    float2 k3 = make_float2(0.f, 0.f);
    if (l > 0)      k1 = __half22float2(*(const __half2*)(qk + kbase - NQK));
    float2 k2 = __half22float2(*(const __half2*)(qk + kbase));
    if (l < Lc - 1) k3 = __half22float2(*(const __half2*)(qk + kbase + NQK));

    float p0 = qv.x * k0.x + qv.y * k0.y;
    float p1 = qv.x * k1.x + qv.y * k1.y;
    float p2 = qv.x * k2.x + qv.y * k2.y;
    float p3 = qv.x * k3.x + qv.y * k3.y;
    #pragma unroll
    for (int o = 16; o; o >>= 1) {
        p0 += __shfl_xor_sync(0xFFFFFFFFu, p0, o);
        p1 += __shfl_xor_sync(0xFFFFFFFFu, p1, o);
        p2 += __shfl_xor_sync(0xFFFFFFFFu, p2, o);
        p3 += __shfl_xor_sync(0xFFFFFFFFu, p3, o);
    }
    const float scale = 0.125f;
    float s0 = p0 * scale, s1 = p1 * scale, s2 = p2 * scale, s3 = p3 * scale;
    float m = fmaxf(fmaxf(s0, s1), fmaxf(s2, s3));
    float e0 = __expf(s0 - m), e1 = __expf(s1 - m),
          e2 = __expf(s2 - m), e3 = __expf(s3 - m);
    float inv = 1.f / (e0 + e1 + e2 + e3);
    float a0 = e0 * inv, a1 = e1 * inv, a2 = e2 * inv, a3 = e3 * inv;

    float ox = a0 * v0.x + a1 * k1.x + a2 * k2.x + a3 * k3.x;
    float oy = a0 * v0.y + a1 * k1.y + a2 * k2.y + a3 * k3.y;

    *(__half2*)(ahi + obase) = __half2(__float2half_rn(ox), __float2half_rn(oy));
}

// ---------------------------------------------------------------------------
extern "C" void kernel_launch(void* const* d_in, const int* in_sizes, int n_in,
                              void* d_out, int out_size)
{
    const float* x    = (const float*)d_in[0];
    const float* ax   = (const float*)d_in[1];
    const float* WQ_w = (const float*)d_in[2];
    const float* WQ_b = (const float*)d_in[3];
    const float* WK_w = (const float*)d_in[4];
    const float* WK_b = (const float*)d_in[5];
    const float* WV_w = (const float*)d_in[6];
    const float* WV_b = (const float*)d_in[7];
    const float* WO_w = (const float*)d_in[8];
    const float* WO_b = (const float*)d_in[9];
    float* out = (float*)d_out;

    float* bqk;
    __half *qkp, *xhi, *ahi, *wqkh, *wqkl, *woh, *wol;
    cudaGetSymbolAddress((void**)&qkp,  g_qk);
    cudaGetSymbolAddress((void**)&bqk,  g_bqk);
    cudaGetSymbolAddress((void**)&xhi,  g_xhi);
    cudaGetSymbolAddress((void**)&ahi,  g_ahi);
    cudaGetSymbolAddress((void**)&wqkh, g_wqkT_hi);
    cudaGetSymbolAddress((void**)&wqkl, g_wqkT_lo);
    cudaGetSymbolAddress((void**)&woh,  g_woT_hi);
    cudaGetSymbolAddress((void**)&wol,  g_woT_lo);

    cudaFuncSetAttribute((const void*)gemm_mma2<true, false>,
                         cudaFuncAttributeMaxDynamicSharedMemorySize, SMEM_REQ);
    cudaFuncSetAttribute((const void*)gemm_mma2<false, true>,
                         cudaFuncAttributeMaxDynamicSharedMemorySize, SMEM_REQ);

    // conversions
    const int n4 = MTOK * HID / 4;
    to_half<<<n4 / 256, 256>>>(x, xhi, n4);
    dim3 tb(32, 8), tg(32, 32, 3);
    transpose_split3<<<tg, tb>>>(
        WQ_w, wqkh,                       wqkl,
        WK_w, wqkh + (size_t)HID * Kdim,  wqkl + (size_t)HID * Kdim,
        WO_w, woh,                        wol);
    cudaMemcpyAsync(bqk,       WQ_b, HID * sizeof(float), cudaMemcpyDeviceToDevice);
    cudaMemcpyAsync(bqk + HID, WK_b, HID * sizeof(float), cudaMemcpyDeviceToDevice);
    proj_small<<<64, 256>>>(ax, WK_w, WK_b, WV_w, WV_b);

    // fused Q|K projection: [MTOK, 2048] fp16, 1-pass (hi-only weights)
    dim3 gqk(NQK / BN, MTOK / BM);   // (16, 128)
    gemm_mma2<true, false><<<gqk, 512, SMEM_REQ>>>(xhi, wqkh, wqkl, bqk, qkp, NQK);

    // attention -> fp16 output
    attn_kernel<<<(Bc * Lc * NH) / 8, 256>>>(qkp, ahi);

    // output projection (fp32 out, 2-pass)
    dim3 go(HID / BN, MTOK / BM);    // (8, 128)
    gemm_mma2<false, true><<<go, 512, SMEM_REQ>>>(ahi, woh, wol, WO_b, out, HID);
}

// round 15
// speedup vs baseline: 2.3713x; 1.1637x over previous
#include <cuda_runtime.h>
#include <cuda_fp16.h>

// ---------------------------------------------------------------------------
// Problem constants
// ---------------------------------------------------------------------------
constexpr int Bc  = 8;
constexpr int Lc  = 4096;
constexpr int NH  = 16;
constexpr int HD  = 64;
constexpr int HID = 1024;
constexpr int MTOK = Bc * Lc;       // 32768
constexpr int Kdim = 1024;
constexpr int NQK  = 2048;          // fused Q|K output width

// GEMM tiling: CTA 256x128, BK=64, 512 threads (16 warps, 4x4), warp 64x32
constexpr int BM = 256, BN = 128, BK = 64;
constexpr int NC = Kdim / BK;       // 16 k-chunks
// stage layout (bytes): A 32K | Bhi 16K | Blo 16K
constexpr int ST_A   = 0;
constexpr int ST_BHI = 32768;
constexpr int ST_BLO = 49152;
constexpr int STAGE_BYTES = 65536;
constexpr int NSLOT = 3;
constexpr int SMEM_REQ = NSLOT * STAGE_BYTES + 1024;

// ---------------------------------------------------------------------------
// Scratch (device globals: no allocation allowed)
// ---------------------------------------------------------------------------
__device__ __half g_qk [(size_t)MTOK * NQK];   // fused Q|K output (fp16)
__device__ float g_ak [Bc * HID];
__device__ float g_av [Bc * HID];
__device__ float g_bqk[NQK];                   // concat bias
__device__ __half g_xhi [(size_t)MTOK * HID];
__device__ __half g_ahi [(size_t)MTOK * HID];  // attention out (fp16 hi)
__device__ __half g_wqkT_hi[(size_t)NQK * Kdim], g_wqkT_lo[(size_t)NQK * Kdim];
__device__ __half g_woT_hi [(size_t)Kdim * HID], g_woT_lo [(size_t)Kdim * HID];

// ---------------------------------------------------------------------------
// helpers
// ---------------------------------------------------------------------------
__device__ __forceinline__ unsigned smem_u32(const void* p) {
    unsigned a;
    asm("{ .reg .u64 t; cvta.to.shared.u64 t, %1; cvt.u32.u64 %0, t; }"
        : "=r"(a) : "l"(p));
    return a;
}
__device__ __forceinline__ void cp16(unsigned saddr, const void* g) {
    asm volatile("cp.async.cg.shared.global [%0], [%1], 16;\n"
                 :: "r"(saddr), "l"(g));
}
#define CP_COMMIT() asm volatile("cp.async.commit_group;\n" ::: "memory")
#define CP_WAIT1()  asm volatile("cp.async.wait_group 1;\n" ::: "memory")
#define CP_WAIT0()  asm volatile("cp.async.wait_group 0;\n" ::: "memory")

__device__ __forceinline__ void ldsm4(unsigned& r0, unsigned& r1,
                                      unsigned& r2, unsigned& r3, unsigned a) {
    asm volatile("ldmatrix.sync.aligned.m8n8.x4.shared.b16 {%0,%1,%2,%3}, [%4];"
                 : "=r"(r0), "=r"(r1), "=r"(r2), "=r"(r3) : "r"(a));
}
__device__ __forceinline__ void mma16816(float* c, const unsigned* a,
                                         const unsigned* b) {
    asm volatile(
        "mma.sync.aligned.m16n8k16.row.col.f32.f16.f16.f32 "
        "{%0,%1,%2,%3}, {%4,%5,%6,%7}, {%8,%9}, {%0,%1,%2,%3};"
        : "+f"(c[0]), "+f"(c[1]), "+f"(c[2]), "+f"(c[3])
        : "r"(a[0]), "r"(a[1]), "r"(a[2]), "r"(a[3]), "r"(b[0]), "r"(b[1]));
}

// ---------------------------------------------------------------------------
// Split-fp16 HMMA GEMM: C[M, N] = Ahi @ (Bhi [+ Blo]) ^T + bias
// B operands transposed: [N, K] K-major. CTA 256x128, BK=64, 16 warps (4x4),
// warp tile 64x32, 3-slot cp.async pipeline (proven: wait -> sync -> load),
// exact tail invariant via empty commit groups.
// HOUT: fp16 output (qk buffer) vs fp32 (final out).
// BLO:  apply the Blo correction pass (2-pass) vs hi-only (1-pass).
// ---------------------------------------------------------------------------
template <bool HOUT, bool BLO>
__global__ __launch_bounds__(512, 1)
void gemm_mma2(const __half* __restrict__ Ahi,
               const __half* __restrict__ Bhi, const __half* __restrict__ Blo,
               const float* __restrict__ bias, void* __restrict__ Cout, int ldc)
{
    extern __shared__ char smem_raw[];
    const unsigned sbase = (smem_u32(smem_raw) + 1023u) & ~1023u;
    const int tid  = threadIdx.x;
    const int wid  = tid >> 5;
    const int lane = tid & 31;
    const int row0 = blockIdx.y * BM;
    const int col0 = blockIdx.x * BN;

    auto load_chunk = [&](int c, int slot) {
        const unsigned sa = sbase + slot * STAGE_BYTES;
        const int kt = c * BK;
        #pragma unroll
        for (int i = 0; i < 4; ++i) {                 // A: 2048 x 16B
            int v = tid + i * 512;
            int r = v >> 3, u = v & 7;                // row 0..255
            unsigned bo = (unsigned)(r * 128 + u * 16);
            unsigned so = bo ^ ((bo >> 3) & 0x70);    // SW128
            cp16(sa + ST_A + so, Ahi + (size_t)(row0 + r) * Kdim + kt + u * 8);
        }
        #pragma unroll
        for (int i = 0; i < 2; ++i) {                 // B hi (+lo): 1024 x 16B each
            int v = tid + i * 512;
            int r = v >> 3, u = v & 7;                // row 0..127
            unsigned bo = (unsigned)(r * 128 + u * 16);
            unsigned so = bo ^ ((bo >> 3) & 0x70);
            size_t go = (size_t)(col0 + r) * Kdim + kt + u * 8;
            cp16(sa + ST_BHI + so, Bhi + go);
            if (BLO) cp16(sa + ST_BLO + so, Blo + go);
        }
        CP_COMMIT();
    };

    // per-lane ldmatrix address components
    const int mrow0 = (wid >> 2) * 64;      // warp M offset (0..192)
    const int nrow0 = (wid & 3) * 32;       // warp N offset (0..96)
    const unsigned rtA  = (lane & 7) + ((lane >> 3) & 1) * 8;
    const unsigned s16A = ((lane >> 4) & 1) * 16;
    const unsigned rtB  = (lane & 7) + ((lane >> 4) & 1) * 8;
    const unsigned s16B = ((lane >> 3) & 1) * 16;
    const unsigned xorv = (lane & 7) * 16;

    float acc[4][4][4];
    #pragma unroll
    for (int mi = 0; mi < 4; ++mi)
        #pragma unroll
        for (int ni = 0; ni < 4; ++ni)
            #pragma unroll
            for (int r = 0; r < 4; ++r) acc[mi][ni][r] = 0.f;

    load_chunk(0, 0);
    load_chunk(1, 1);

    for (int c = 0; c < NC; ++c) {
        const int slot = c % NSLOT;
        CP_WAIT1();                      // chunk c landed (this thread's part)
        __syncthreads();                 // cross-thread visibility; slot free
        if (c + 2 < NC) load_chunk(c + 2, (c + 2) % NSLOT);
        else            CP_COMMIT();     // empty group keeps invariant exact

        const unsigned sa   = sbase + slot * STAGE_BYTES;
        const unsigned pA   = sa + ST_A   + (mrow0 + rtA) * 128;
        const unsigned pBhi = sa + ST_BHI + (nrow0 + rtB) * 128;
        const unsigned pBlo = sa + ST_BLO + (nrow0 + rtB) * 128;

        #pragma unroll
        for (int kk = 0; kk < 4; ++kk) {
            const unsigned colA = ((unsigned)(kk * 32) + s16A) ^ xorv;
            const unsigned colB = ((unsigned)(kk * 32) + s16B) ^ xorv;
            unsigned ah[4][4], bh[2][4], bl[2][4];
            #pragma unroll
            for (int mi = 0; mi < 4; ++mi)
                ldsm4(ah[mi][0], ah[mi][1], ah[mi][2], ah[mi][3],
                      pA + mi * 2048 + colA);
            #pragma unroll
            for (int nb = 0; nb < 2; ++nb) {
                ldsm4(bh[nb][0], bh[nb][1], bh[nb][2], bh[nb][3],
                      pBhi + nb * 2048 + colB);
                if (BLO)
                    ldsm4(bl[nb][0], bl[nb][1], bl[nb][2], bl[nb][3],
                          pBlo + nb * 2048 + colB);
            }
            #pragma unroll
            for (int mi = 0; mi < 4; ++mi)
                #pragma unroll
                for (int ni = 0; ni < 4; ++ni) {
                    const unsigned* bhp = &bh[ni >> 1][(ni & 1) * 2];
                    mma16816(acc[mi][ni], ah[mi], bhp);            // A*Bhi
                    if (BLO) {
                        const unsigned* blp = &bl[ni >> 1][(ni & 1) * 2];
                        mma16816(acc[mi][ni], ah[mi], blp);        // A*Blo
                    }
                }
        }
    }
    CP_WAIT0();

    // epilogue: acc + bias -> C (fp16 or fp32)
    #pragma unroll
    for (int ni = 0; ni < 4; ++ni) {
        const int cc = col0 + nrow0 + ni * 8 + (lane & 3) * 2;
        const float b0 = bias[cc], b1 = bias[cc + 1];
        #pragma unroll
        for (int mi = 0; mi < 4; ++mi) {
            const int r = row0 + mrow0 + mi * 16 + (lane >> 2);
            if (HOUT) {
                __half* C = (__half*)Cout;
                *(__half2*)(C + (size_t)r * ldc + cc) =
                    __half2(__float2half_rn(acc[mi][ni][0] + b0),
                            __float2half_rn(acc[mi][ni][1] + b1));
                *(__half2*)(C + (size_t)(r + 8) * ldc + cc) =
                    __half2(__float2half_rn(acc[mi][ni][2] + b0),
                            __float2half_rn(acc[mi][ni][3] + b1));
            } else {
                float* C = (float*)Cout;
                *(float2*)(C + (size_t)r * ldc + cc) =
                    make_float2(acc[mi][ni][0] + b0, acc[mi][ni][1] + b1);
                *(float2*)(C + (size_t)(r + 8) * ldc + cc) =
                    make_float2(acc[mi][ni][2] + b0, acc[mi][ni][3] + b1);
            }
        }
    }
}

// ---------------------------------------------------------------------------
// fp32 -> fp16 convert (hi only), vectorized
// ---------------------------------------------------------------------------
__global__ __launch_bounds__(256)
void to_half(const float* __restrict__ in, __half* __restrict__ out, int n4)
{
    int i = blockIdx.x * blockDim.x + threadIdx.x;
    if (i >= n4) return;
    float4 v = ((const float4*)in)[i];
    __half2* op = (__half2*)(out + (size_t)i * 4);
    op[0] = __half2(__float2half_rn(v.x), __float2half_rn(v.y));
    op[1] = __half2(__float2half_rn(v.z), __float2half_rn(v.w));
}

// ---------------------------------------------------------------------------
// Batched: W [K,N] fp32 -> W^T hi/lo fp16 [N,K], 3 weights in one launch (z)
// ---------------------------------------------------------------------------
__global__ __launch_bounds__(256)
void transpose_split3(const float* __restrict__ W0, __half* __restrict__ H0, __half* __restrict__ L0,
                      const float* __restrict__ W1, __half* __restrict__ H1, __half* __restrict__ L1,
                      const float* __restrict__ W2, __half* __restrict__ H2, __half* __restrict__ L2)
{
    const float* W; __half *Th, *Tl;
    if      (blockIdx.z == 0) { W = W0; Th = H0; Tl = L0; }
    else if (blockIdx.z == 1) { W = W1; Th = H1; Tl = L1; }
    else                      { W = W2; Th = H2; Tl = L2; }

    __shared__ float t[32][33];
    const int tx = threadIdx.x, ty = threadIdx.y;   // (32, 8)
    const int n0 = blockIdx.x * 32, k0 = blockIdx.y * 32;
    #pragma unroll
    for (int i = 0; i < 32; i += 8)
        t[ty + i][tx] = W[(size_t)(k0 + ty + i) * HID + n0 + tx];
    __syncthreads();
    #pragma unroll
    for (int i = 0; i < 32; i += 8) {
        float v = t[tx][ty + i];
        __half h = __float2half_rn(v);
        __half l = __float2half_rn(v - __half2float(h));
        Th[(size_t)(n0 + ty + i) * Kdim + k0 + tx] = h;
        Tl[(size_t)(n0 + ty + i) * Kdim + k0 + tx] = l;
    }
}

// ---------------------------------------------------------------------------
// Tiny projections: ak = ax@WK + bK, av = ax@WV + bV (fp32, 8x1024 each)
// ---------------------------------------------------------------------------
__global__ __launch_bounds__(256)
void proj_small(const float* __restrict__ ax,
                const float* __restrict__ WK, const float* __restrict__ WKb,
                const float* __restrict__ WV, const float* __restrict__ WVb)
{
    __shared__ float xs[HID];
    const int sel = blockIdx.x >> 5;
    const int bb  = (blockIdx.x >> 2) & 7;
    const int n   = ((blockIdx.x & 3) << 8) + threadIdx.x;
    for (int i = threadIdx.x; i < HID; i += 256) xs[i] = ax[bb * HID + i];
    __syncthreads();
    const float* W    = sel ? WV  : WK;
    const float* bias = sel ? WVb : WKb;
    float acc = 0.f;
    #pragma unroll 8
    for (int kk = 0; kk < HID; ++kk)
        acc = fmaf(xs[kk], W[(size_t)kk * HID + n], acc);
    float* o = sel ? g_av : g_ak;
    o[bb * HID + n] = acc + bias[n];
}

// ---------------------------------------------------------------------------
// Attention on fused fp16 qk buffer (row stride NQK), emits fp16 output.
// ---------------------------------------------------------------------------
__global__ __launch_bounds__(256)
void attn_kernel(const __half* __restrict__ qk, __half* __restrict__ ahi)
{
    const int w    = (blockIdx.x * blockDim.x + threadIdx.x) >> 5;
    const int lane = threadIdx.x & 31;
    const int h = w & 15;
    const int l = (w >> 4) & (Lc - 1);
    const int b = w >> 16;

    const size_t tok   = (size_t)(b * Lc + l);
    const size_t qbase = tok * NQK + h * HD + lane * 2;          // q cols
    const size_t kbase = qbase + HID;                            // k cols
    const size_t obase = tok * HID + h * HD + lane * 2;
    const size_t gbase = (size_t)b * HID + h * HD + lane * 2;

    float2 qv = __half22float2(*(const __half2*)(qk + qbase));
    float2 k0 = *(const float2*)(g_ak + gbase);
    float2 v0 = *(const float2*)(g_av + gbase);
    float2 k1 = make_float2(0.f, 0.f);
    float2 k3 = make_float2(0.f, 0.f);
    if (l > 0)      k1 = __half22float2(*(const __half2*)(qk + kbase - NQK));
    float2 k2 = __half22float2(*(const __half2*)(qk + kbase));
    if (l < Lc - 1) k3 = __half22float2(*(const __half2*)(qk + kbase + NQK));

    float p0 = qv.x * k0.x + qv.y * k0.y;
    float p1 = qv.x * k1.x + qv.y * k1.y;
    float p2 = qv.x * k2.x + qv.y * k2.y;
    float p3 = qv.x * k3.x + qv.y * k3.y;
    #pragma unroll
    for (int o = 16; o; o >>= 1) {
        p0 += __shfl_xor_sync(0xFFFFFFFFu, p0, o);
        p1 += __shfl_xor_sync(0xFFFFFFFFu, p1, o);
        p2 += __shfl_xor_sync(0xFFFFFFFFu, p2, o);
        p3 += __shfl_xor_sync(0xFFFFFFFFu, p3, o);
    }
    const float scale = 0.125f;
    float s0 = p0 * scale, s1 = p1 * scale, s2 = p2 * scale, s3 = p3 * scale;
    float m = fmaxf(fmaxf(s0, s1), fmaxf(s2, s3));
    float e0 = __expf(s0 - m), e1 = __expf(s1 - m),
          e2 = __expf(s2 - m), e3 = __expf(s3 - m);
    float inv = 1.f / (e0 + e1 + e2 + e3);
    float a0 = e0 * inv, a1 = e1 * inv, a2 = e2 * inv, a3 = e3 * inv;

    float ox = a0 * v0.x + a1 * k1.x + a2 * k2.x + a3 * k3.x;
    float oy = a0 * v0.y + a1 * k1.y + a2 * k2.y + a3 * k3.y;

    *(__half2*)(ahi + obase) = __half2(__float2half_rn(ox), __float2half_rn(oy));
}

// ---------------------------------------------------------------------------
extern "C" void kernel_launch(void* const* d_in, const int* in_sizes, int n_in,
                              void* d_out, int out_size)
{
    const float* x    = (const float*)d_in[0];
    const float* ax   = (const float*)d_in[1];
    const float* WQ_w = (const float*)d_in[2];
    const float* WQ_b = (const float*)d_in[3];
    const float* WK_w = (const float*)d_in[4];
    const float* WK_b = (const float*)d_in[5];
    const float* WV_w = (const float*)d_in[6];
    const float* WV_b = (const float*)d_in[7];
    const float* WO_w = (const float*)d_in[8];
    const float* WO_b = (const float*)d_in[9];
    float* out = (float*)d_out;

    float* bqk;
    __half *qkp, *xhi, *ahi, *wqkh, *wqkl, *woh, *wol;
    cudaGetSymbolAddress((void**)&qkp,  g_qk);
    cudaGetSymbolAddress((void**)&bqk,  g_bqk);
    cudaGetSymbolAddress((void**)&xhi,  g_xhi);
    cudaGetSymbolAddress((void**)&ahi,  g_ahi);
    cudaGetSymbolAddress((void**)&wqkh, g_wqkT_hi);
    cudaGetSymbolAddress((void**)&wqkl, g_wqkT_lo);
    cudaGetSymbolAddress((void**)&woh,  g_woT_hi);
    cudaGetSymbolAddress((void**)&wol,  g_woT_lo);

    cudaFuncSetAttribute((const void*)gemm_mma2<true, false>,
                         cudaFuncAttributeMaxDynamicSharedMemorySize, SMEM_REQ);
    cudaFuncSetAttribute((const void*)gemm_mma2<false, false>,
                         cudaFuncAttributeMaxDynamicSharedMemorySize, SMEM_REQ);

    // conversions
    const int n4 = MTOK * HID / 4;
    to_half<<<n4 / 256, 256>>>(x, xhi, n4);
    dim3 tb(32, 8), tg(32, 32, 3);
    transpose_split3<<<tg, tb>>>(
        WQ_w, wqkh,                       wqkl,
        WK_w, wqkh + (size_t)HID * Kdim,  wqkl + (size_t)HID * Kdim,
        WO_w, woh,                        wol);
    cudaMemcpyAsync(bqk,       WQ_b, HID * sizeof(float), cudaMemcpyDeviceToDevice);
    cudaMemcpyAsync(bqk + HID, WK_b, HID * sizeof(float), cudaMemcpyDeviceToDevice);
    proj_small<<<64, 256>>>(ax, WK_w, WK_b, WV_w, WV_b);

    // fused Q|K projection: [MTOK, 2048] fp16, 1-pass (hi-only weights)
    dim3 gqk(NQK / BN, MTOK / BM);   // (16, 128)
    gemm_mma2<true, false><<<gqk, 512, SMEM_REQ>>>(xhi, wqkh, wqkl, bqk, qkp, NQK);

    // attention -> fp16 output
    attn_kernel<<<(Bc * Lc * NH) / 8, 256>>>(qkp, ahi);

    // output projection (fp32 out, 1-pass)
    dim3 go(HID / BN, MTOK / BM);    // (8, 128)
    gemm_mma2<false, false><<<go, 512, SMEM_REQ>>>(ahi, woh, wol, WO_b, out, HID);
}

// round 16
// speedup vs baseline: 2.5425x; 1.0722x over previous
#include <cuda_runtime.h>
#include <cuda_fp16.h>

// ---------------------------------------------------------------------------
// Problem constants
// ---------------------------------------------------------------------------
constexpr int Bc  = 8;
constexpr int Lc  = 4096;
constexpr int NH  = 16;
constexpr int HD  = 64;
constexpr int HID = 1024;
constexpr int MTOK = Bc * Lc;       // 32768
constexpr int Kdim = 1024;
constexpr int NQK  = 2048;          // fused Q|K output width

// GEMM tiling: CTA 128x128, BK=64, 256 threads (8 warps, 2x4), warp 64x32,
// 2 CTAs per SM (smem 97KB/CTA, 128 regs/thread).
constexpr int BM = 128, BN = 128, BK = 64;
constexpr int NC = Kdim / BK;       // 16 k-chunks
// stage layout (bytes): A 16K | B 16K
constexpr int ST_A = 0;
constexpr int ST_B = 16384;
constexpr int STAGE_BYTES = 32768;
constexpr int NSLOT = 3;
constexpr int SMEM_REQ = NSLOT * STAGE_BYTES + 1024;   // ~97 KB

// ---------------------------------------------------------------------------
// Scratch (device globals: no allocation allowed)
// ---------------------------------------------------------------------------
__device__ __half g_qk [(size_t)MTOK * NQK];   // fused Q|K output (fp16)
__device__ float g_ak [Bc * HID];
__device__ float g_av [Bc * HID];
__device__ float g_bqk[NQK];                   // concat bias
__device__ __half g_xhi [(size_t)MTOK * HID];
__device__ __half g_ahi [(size_t)MTOK * HID];  // attention out (fp16)
__device__ __half g_wqkT[(size_t)NQK * Kdim];  // WQ|WK transposed, fp16
__device__ __half g_woT [(size_t)Kdim * HID];  // WO transposed, fp16

// ---------------------------------------------------------------------------
// helpers
// ---------------------------------------------------------------------------
__device__ __forceinline__ unsigned smem_u32(const void* p) {
    unsigned a;
    asm("{ .reg .u64 t; cvta.to.shared.u64 t, %1; cvt.u32.u64 %0, t; }"
        : "=r"(a) : "l"(p));
    return a;
}
__device__ __forceinline__ void cp16(unsigned saddr, const void* g) {
    asm volatile("cp.async.cg.shared.global [%0], [%1], 16;\n"
                 :: "r"(saddr), "l"(g));
}
#define CP_COMMIT() asm volatile("cp.async.commit_group;\n" ::: "memory")
#define CP_WAIT1()  asm volatile("cp.async.wait_group 1;\n" ::: "memory")
#define CP_WAIT0()  asm volatile("cp.async.wait_group 0;\n" ::: "memory")

__device__ __forceinline__ void ldsm4(unsigned& r0, unsigned& r1,
                                      unsigned& r2, unsigned& r3, unsigned a) {
    asm volatile("ldmatrix.sync.aligned.m8n8.x4.shared.b16 {%0,%1,%2,%3}, [%4];"
                 : "=r"(r0), "=r"(r1), "=r"(r2), "=r"(r3) : "r"(a));
}
__device__ __forceinline__ void mma16816(float* c, const unsigned* a,
                                         const unsigned* b) {
    asm volatile(
        "mma.sync.aligned.m16n8k16.row.col.f32.f16.f16.f32 "
        "{%0,%1,%2,%3}, {%4,%5,%6,%7}, {%8,%9}, {%0,%1,%2,%3};"
        : "+f"(c[0]), "+f"(c[1]), "+f"(c[2]), "+f"(c[3])
        : "r"(a[0]), "r"(a[1]), "r"(a[2]), "r"(a[3]), "r"(b[0]), "r"(b[1]));
}

// ---------------------------------------------------------------------------
// 1-pass fp16 HMMA GEMM: C[M, N] = A @ B^T + bias  (B given [N,K] K-major)
// CTA 128x128, BK=64, 8 warps (2x4), warp tile 64x32, 3-slot cp.async
// pipeline (proven: wait -> sync -> load), exact tail invariant via empty
// commit groups, 2 CTAs/SM so barrier bubbles overlap across CTAs.
// HOUT: fp16 output (qk buffer) vs fp32 (final out).
// ---------------------------------------------------------------------------
template <bool HOUT>
__global__ __launch_bounds__(256, 2)
void gemm_h1(const __half* __restrict__ A, const __half* __restrict__ B,
             const float* __restrict__ bias, void* __restrict__ Cout, int ldc)
{
    extern __shared__ char smem_raw[];
    const unsigned sbase = (smem_u32(smem_raw) + 1023u) & ~1023u;
    const int tid  = threadIdx.x;
    const int wid  = tid >> 5;
    const int lane = tid & 31;
    const int row0 = blockIdx.y * BM;
    const int col0 = blockIdx.x * BN;

    auto load_chunk = [&](int c, int slot) {
        const unsigned sa = sbase + slot * STAGE_BYTES;
        const int kt = c * BK;
        #pragma unroll
        for (int i = 0; i < 4; ++i) {                 // A + B: 1024 x 16B each
            int v = tid + i * 256;                    // 0..1023
            int r = v >> 3, u = v & 7;                // row 0..127
            unsigned bo = (unsigned)(r * 128 + u * 16);
            unsigned so = bo ^ ((bo >> 3) & 0x70);    // SW128
            cp16(sa + ST_A + so, A + (size_t)(row0 + r) * Kdim + kt + u * 8);
            cp16(sa + ST_B + so, B + (size_t)(col0 + r) * Kdim + kt + u * 8);
        }
        CP_COMMIT();
    };

    // per-lane ldmatrix address components
    const int mrow0 = (wid >> 2) * 64;      // warp M offset (0 or 64)
    const int nrow0 = (wid & 3) * 32;       // warp N offset (0..96)
    const unsigned rtA  = (lane & 7) + ((lane >> 3) & 1) * 8;
    const unsigned s16A = ((lane >> 4) & 1) * 16;
    const unsigned rtB  = (lane & 7) + ((lane >> 4) & 1) * 8;
    const unsigned s16B = ((lane >> 3) & 1) * 16;
    const unsigned xorv = (lane & 7) * 16;

    float acc[4][4][4];
    #pragma unroll
    for (int mi = 0; mi < 4; ++mi)
        #pragma unroll
        for (int ni = 0; ni < 4; ++ni)
            #pragma unroll
            for (int r = 0; r < 4; ++r) acc[mi][ni][r] = 0.f;

    load_chunk(0, 0);
    load_chunk(1, 1);

    for (int c = 0; c < NC; ++c) {
        const int slot = c % NSLOT;
        CP_WAIT1();                      // chunk c landed (this thread's part)
        __syncthreads();                 // cross-thread visibility; slot free
        if (c + 2 < NC) load_chunk(c + 2, (c + 2) % NSLOT);
        else            CP_COMMIT();     // empty group keeps invariant exact

        const unsigned sa = sbase + slot * STAGE_BYTES;
        const unsigned pA = sa + ST_A + (mrow0 + rtA) * 128;
        const unsigned pB = sa + ST_B + (nrow0 + rtB) * 128;

        #pragma unroll
        for (int kk = 0; kk < 4; ++kk) {
            const unsigned colA = ((unsigned)(kk * 32) + s16A) ^ xorv;
            const unsigned colB = ((unsigned)(kk * 32) + s16B) ^ xorv;
            unsigned ah[4][4], bh[2][4];
            #pragma unroll
            for (int mi = 0; mi < 4; ++mi)
                ldsm4(ah[mi][0], ah[mi][1], ah[mi][2], ah[mi][3],
                      pA + mi * 2048 + colA);
            #pragma unroll
            for (int nb = 0; nb < 2; ++nb)
                ldsm4(bh[nb][0], bh[nb][1], bh[nb][2], bh[nb][3],
                      pB + nb * 2048 + colB);
            #pragma unroll
            for (int mi = 0; mi < 4; ++mi)
                #pragma unroll
                for (int ni = 0; ni < 4; ++ni)
                    mma16816(acc[mi][ni], ah[mi], &bh[ni >> 1][(ni & 1) * 2]);
        }
    }
    CP_WAIT0();

    // epilogue: acc + bias -> C (fp16 or fp32)
    #pragma unroll
    for (int ni = 0; ni < 4; ++ni) {
        const int cc = col0 + nrow0 + ni * 8 + (lane & 3) * 2;
        const float b0 = bias[cc], b1 = bias[cc + 1];
        #pragma unroll
        for (int mi = 0; mi < 4; ++mi) {
            const int r = row0 + mrow0 + mi * 16 + (lane >> 2);
            if (HOUT) {
                __half* C = (__half*)Cout;
                *(__half2*)(C + (size_t)r * ldc + cc) =
                    __half2(__float2half_rn(acc[mi][ni][0] + b0),
                            __float2half_rn(acc[mi][ni][1] + b1));
                *(__half2*)(C + (size_t)(r + 8) * ldc + cc) =
                    __half2(__float2half_rn(acc[mi][ni][2] + b0),
                            __float2half_rn(acc[mi][ni][3] + b1));
            } else {
                float* C = (float*)Cout;
                *(float2*)(C + (size_t)r * ldc + cc) =
                    make_float2(acc[mi][ni][0] + b0, acc[mi][ni][1] + b1);
                *(float2*)(C + (size_t)(r + 8) * ldc + cc) =
                    make_float2(acc[mi][ni][2] + b0, acc[mi][ni][3] + b1);
            }
        }
    }
}

// ---------------------------------------------------------------------------
// fp32 -> fp16 convert, vectorized
// ---------------------------------------------------------------------------
__global__ __launch_bounds__(256)
void to_half(const float* __restrict__ in, __half* __restrict__ out, int n4)
{
    int i = blockIdx.x * blockDim.x + threadIdx.x;
    if (i >= n4) return;
    float4 v = ((const float4*)in)[i];
    __half2* op = (__half2*)(out + (size_t)i * 4);
    op[0] = __half2(__float2half_rn(v.x), __float2half_rn(v.y));
    op[1] = __half2(__float2half_rn(v.z), __float2half_rn(v.w));
}

// ---------------------------------------------------------------------------
// Batched: W [K,N] fp32 -> W^T fp16 [N,K], 3 weights in one launch (z)
// ---------------------------------------------------------------------------
__global__ __launch_bounds__(256)
void transpose3(const float* __restrict__ W0, __half* __restrict__ T0,
                const float* __restrict__ W1, __half* __restrict__ T1,
                const float* __restrict__ W2, __half* __restrict__ T2)
{
    const float* W; __half* T;
    if      (blockIdx.z == 0) { W = W0; T = T0; }
    else if (blockIdx.z == 1) { W = W1; T = T1; }
    else                      { W = W2; T = T2; }

    __shared__ float t[32][33];
    const int tx = threadIdx.x, ty = threadIdx.y;   // (32, 8)
    const int n0 = blockIdx.x * 32, k0 = blockIdx.y * 32;
    #pragma unroll
    for (int i = 0; i < 32; i += 8)
        t[ty + i][tx] = W[(size_t)(k0 + ty + i) * HID + n0 + tx];
    __syncthreads();
    #pragma unroll
    for (int i = 0; i < 32; i += 8)
        T[(size_t)(n0 + ty + i) * Kdim + k0 + tx] =
            __float2half_rn(t[tx][ty + i]);
}

// ---------------------------------------------------------------------------
// Tiny projections: ak = ax@WK + bK, av = ax@WV + bV (fp32, 8x1024 each)
// ---------------------------------------------------------------------------
__global__ __launch_bounds__(256)
void proj_small(const float* __restrict__ ax,
                const float* __restrict__ WK, const float* __restrict__ WKb,
                const float* __restrict__ WV, const float* __restrict__ WVb)
{
    __shared__ float xs[HID];
    const int sel = blockIdx.x >> 5;
    const int bb  = (blockIdx.x >> 2) & 7;
    const int n   = ((blockIdx.x & 3) << 8) + threadIdx.x;
    for (int i = threadIdx.x; i < HID; i += 256) xs[i] = ax[bb * HID + i];
    __syncthreads();
    const float* W    = sel ? WV  : WK;
    const float* bias = sel ? WVb : WKb;
    float acc = 0.f;
    #pragma unroll 8
    for (int kk = 0; kk < HID; ++kk)
        acc = fmaf(xs[kk], W[(size_t)kk * HID + n], acc);
    float* o = sel ? g_av : g_ak;
    o[bb * HID + n] = acc + bias[n];
}

// ---------------------------------------------------------------------------
// Attention on fused fp16 qk buffer (row stride NQK), emits fp16 output.
// ---------------------------------------------------------------------------
__global__ __launch_bounds__(256)
void attn_kernel(const __half* __restrict__ qk, __half* __restrict__ ahi)
{
    const int w    = (blockIdx.x * blockDim.x + threadIdx.x) >> 5;
    const int lane = threadIdx.x & 31;
    const int h = w & 15;
    const int l = (w >> 4) & (Lc - 1);
    const int b = w >> 16;

    const size_t tok   = (size_t)(b * Lc + l);
    const size_t qbase = tok * NQK + h * HD + lane * 2;          // q cols
    const size_t kbase = qbase + HID;                            // k cols
    const size_t obase = tok * HID + h * HD + lane * 2;
    const size_t gbase = (size_t)b * HID + h * HD + lane * 2;

    float2 qv = __half22float2(*(const __half2*)(qk + qbase));
    float2 k0 = *(const float2*)(g_ak + gbase);
    float2 v0 = *(const float2*)(g_av + gbase);
    float2 k1 = make_float2(0.f, 0.f);
    float2 k3 = make_float2(0.f, 0.f);
    if (l > 0)      k1 = __half22float2(*(const __half2*)(qk + kbase - NQK));
    float2 k2 = __half22float2(*(const __half2*)(qk + kbase));
    if (l < Lc - 1) k3 = __half22float2(*(const __half2*)(qk + kbase + NQK));

    float p0 = qv.x * k0.x + qv.y * k0.y;
    float p1 = qv.x * k1.x + qv.y * k1.y;
    float p2 = qv.x * k2.x + qv.y * k2.y;
    float p3 = qv.x * k3.x + qv.y * k3.y;
    #pragma unroll
    for (int o = 16; o; o >>= 1) {
        p0 += __shfl_xor_sync(0xFFFFFFFFu, p0, o);
        p1 += __shfl_xor_sync(0xFFFFFFFFu, p1, o);
        p2 += __shfl_xor_sync(0xFFFFFFFFu, p2, o);
        p3 += __shfl_xor_sync(0xFFFFFFFFu, p3, o);
    }
    const float scale = 0.125f;
    float s0 = p0 * scale, s1 = p1 * scale, s2 = p2 * scale, s3 = p3 * scale;
    float m = fmaxf(fmaxf(s0, s1), fmaxf(s2, s3));
    float e0 = __expf(s0 - m), e1 = __expf(s1 - m),
          e2 = __expf(s2 - m), e3 = __expf(s3 - m);
    float inv = 1.f / (e0 + e1 + e2 + e3);
    float a0 = e0 * inv, a1 = e1 * inv, a2 = e2 * inv, a3 = e3 * inv;

    float ox = a0 * v0.x + a1 * k1.x + a2 * k2.x + a3 * k3.x;
    float oy = a0 * v0.y + a1 * k1.y + a2 * k2.y + a3 * k3.y;

    *(__half2*)(ahi + obase) = __half2(__float2half_rn(ox), __float2half_rn(oy));
}

// ---------------------------------------------------------------------------
extern "C" void kernel_launch(void* const* d_in, const int* in_sizes, int n_in,
                              void* d_out, int out_size)
{
    const float* x    = (const float*)d_in[0];
    const float* ax   = (const float*)d_in[1];
    const float* WQ_w = (const float*)d_in[2];
    const float* WQ_b = (const float*)d_in[3];
    const float* WK_w = (const float*)d_in[4];
    const float* WK_b = (const float*)d_in[5];
    const float* WV_w = (const float*)d_in[6];
    const float* WV_b = (const float*)d_in[7];
    const float* WO_w = (const float*)d_in[8];
    const float* WO_b = (const float*)d_in[9];
    float* out = (float*)d_out;

    float* bqk;
    __half *qkp, *xhi, *ahi, *wqkT, *woT;
    cudaGetSymbolAddress((void**)&qkp,  g_qk);
    cudaGetSymbolAddress((void**)&bqk,  g_bqk);
    cudaGetSymbolAddress((void**)&xhi,  g_xhi);
    cudaGetSymbolAddress((void**)&ahi,  g_ahi);
    cudaGetSymbolAddress((void**)&wqkT, g_wqkT);
    cudaGetSymbolAddress((void**)&woT,  g_woT);

    cudaFuncSetAttribute((const void*)gemm_h1<true>,
                         cudaFuncAttributeMaxDynamicSharedMemorySize, SMEM_REQ);
    cudaFuncSetAttribute((const void*)gemm_h1<false>,
                         cudaFuncAttributeMaxDynamicSharedMemorySize, SMEM_REQ);

    // conversions
    const int n4 = MTOK * HID / 4;
    to_half<<<n4 / 256, 256>>>(x, xhi, n4);
    dim3 tb(32, 8), tg(32, 32, 3);
    transpose3<<<tg, tb>>>(WQ_w, wqkT,
                           WK_w, wqkT + (size_t)HID * Kdim,
                           WO_w, woT);
    cudaMemcpyAsync(bqk,       WQ_b, HID * sizeof(float), cudaMemcpyDeviceToDevice);
    cudaMemcpyAsync(bqk + HID, WK_b, HID * sizeof(float), cudaMemcpyDeviceToDevice);
    proj_small<<<64, 256>>>(ax, WK_w, WK_b, WV_w, WV_b);

    // fused Q|K projection: [MTOK, 2048] fp16, 1-pass
    dim3 gqk(NQK / BN, MTOK / BM);   // (16, 256)
    gemm_h1<true><<<gqk, 256, SMEM_REQ>>>(xhi, wqkT, bqk, qkp, NQK);

    // attention -> fp16 output
    attn_kernel<<<(Bc * Lc * NH) / 8, 256>>>(qkp, ahi);

    // output projection (fp32 out, 1-pass)
    dim3 go(HID / BN, MTOK / BM);    // (8, 256)
    gemm_h1<false><<<go, 256, SMEM_REQ>>>(ahi, woT, WO_b, out, HID);
}

// round 17
// speedup vs baseline: 2.7196x; 1.0697x over previous
#include <cuda_runtime.h>
#include <cuda_fp16.h>

// ---------------------------------------------------------------------------
// Problem constants
// ---------------------------------------------------------------------------
constexpr int Bc  = 8;
constexpr int Lc  = 4096;
constexpr int NH  = 16;
constexpr int HD  = 64;
constexpr int HID = 1024;
constexpr int MTOK = Bc * Lc;       // 32768
constexpr int Kdim = 1024;
constexpr int NQK  = 2048;          // fused Q|K output width

// GEMM tiling: CTA 128x128, BK=64, 256 threads (8 warps, 2x4), warp 64x32,
// 2 CTAs per SM (smem 97KB/CTA, ~126 regs/thread).
constexpr int BM = 128, BN = 128, BK = 64;
constexpr int NC = Kdim / BK;       // 16 k-chunks
constexpr int ST_A = 0;
constexpr int ST_B = 16384;
constexpr int STAGE_BYTES = 32768;
constexpr int NSLOT = 3;
constexpr int SMEM_REQ = NSLOT * STAGE_BYTES + 1024;   // ~97 KB

// prologue fused-kernel block ranges
constexpr int N4        = MTOK * HID / 4;      // 8388608 float4s
constexpr int NB_TOHALF = N4 / 256;            // 32768
constexpr int NB_TRANS  = 32 * 32 * 3;         // 3072
constexpr int NB_PROJ   = 64;
constexpr int NB_BIAS   = NQK / 256;           // 8
constexpr int NB_PRO    = NB_TOHALF + NB_TRANS + NB_PROJ + NB_BIAS;

// ---------------------------------------------------------------------------
// Scratch (device globals: no allocation allowed)
// ---------------------------------------------------------------------------
__device__ __half g_qk [(size_t)MTOK * NQK];   // fused Q|K output (fp16)
__device__ float g_ak [Bc * HID];
__device__ float g_av [Bc * HID];
__device__ float g_bqk[NQK];                   // concat bias
__device__ __half g_xhi [(size_t)MTOK * HID];
__device__ __half g_ahi [(size_t)MTOK * HID];  // attention out (fp16)
__device__ __half g_wqkT[(size_t)NQK * Kdim];  // WQ|WK transposed, fp16
__device__ __half g_woT [(size_t)Kdim * HID];  // WO transposed, fp16

// ---------------------------------------------------------------------------
// helpers
// ---------------------------------------------------------------------------
__device__ __forceinline__ unsigned smem_u32(const void* p) {
    unsigned a;
    asm("{ .reg .u64 t; cvta.to.shared.u64 t, %1; cvt.u32.u64 %0, t; }"
        : "=r"(a) : "l"(p));
    return a;
}
__device__ __forceinline__ void cp16(unsigned saddr, const void* g) {
    asm volatile("cp.async.cg.shared.global [%0], [%1], 16;\n"
                 :: "r"(saddr), "l"(g));
}
#define CP_COMMIT() asm volatile("cp.async.commit_group;\n" ::: "memory")
#define CP_WAIT1()  asm volatile("cp.async.wait_group 1;\n" ::: "memory")
#define CP_WAIT0()  asm volatile("cp.async.wait_group 0;\n" ::: "memory")

__device__ __forceinline__ void ldsm4(unsigned& r0, unsigned& r1,
                                      unsigned& r2, unsigned& r3, unsigned a) {
    asm volatile("ldmatrix.sync.aligned.m8n8.x4.shared.b16 {%0,%1,%2,%3}, [%4];"
                 : "=r"(r0), "=r"(r1), "=r"(r2), "=r"(r3) : "r"(a));
}
__device__ __forceinline__ void mma16816(float* c, const unsigned* a,
                                         const unsigned* b) {
    asm volatile(
        "mma.sync.aligned.m16n8k16.row.col.f32.f16.f16.f32 "
        "{%0,%1,%2,%3}, {%4,%5,%6,%7}, {%8,%9}, {%0,%1,%2,%3};"
        : "+f"(c[0]), "+f"(c[1]), "+f"(c[2]), "+f"(c[3])
        : "r"(a[0]), "r"(a[1]), "r"(a[2]), "r"(a[3]), "r"(b[0]), "r"(b[1]));
}
__device__ __forceinline__ float4 ldh4(const __half* p) {
    uint2 u = *(const uint2*)p;
    float2 a = __half22float2(*(__half2*)&u.x);
    float2 b = __half22float2(*(__half2*)&u.y);
    return make_float4(a.x, a.y, b.x, b.y);
}

// ---------------------------------------------------------------------------
// 1-pass fp16 HMMA GEMM: C[M, N] = A @ B^T + bias  (B given [N,K] K-major)
// CTA 128x128, BK=64, 8 warps (2x4), warp tile 64x32, 3-slot cp.async
// pipeline (proven: wait -> sync -> load), exact tail invariant via empty
// commit groups, 2 CTAs/SM. HOUT: fp16 vs fp32 output.
// ---------------------------------------------------------------------------
template <bool HOUT>
__global__ __launch_bounds__(256, 2)
void gemm_h1(const __half* __restrict__ A, const __half* __restrict__ B,
             const float* __restrict__ bias, void* __restrict__ Cout, int ldc)
{
    extern __shared__ char smem_raw[];
    const unsigned sbase = (smem_u32(smem_raw) + 1023u) & ~1023u;
    const int tid  = threadIdx.x;
    const int wid  = tid >> 5;
    const int lane = tid & 31;
    const int row0 = blockIdx.y * BM;
    const int col0 = blockIdx.x * BN;

    auto load_chunk = [&](int c, int slot) {
        const unsigned sa = sbase + slot * STAGE_BYTES;
        const int kt = c * BK;
        #pragma unroll
        for (int i = 0; i < 4; ++i) {                 // A + B: 1024 x 16B each
            int v = tid + i * 256;                    // 0..1023
            int r = v >> 3, u = v & 7;                // row 0..127
            unsigned bo = (unsigned)(r * 128 + u * 16);
            unsigned so = bo ^ ((bo >> 3) & 0x70);    // SW128
            cp16(sa + ST_A + so, A + (size_t)(row0 + r) * Kdim + kt + u * 8);
            cp16(sa + ST_B + so, B + (size_t)(col0 + r) * Kdim + kt + u * 8);
        }
        CP_COMMIT();
    };

    const int mrow0 = (wid >> 2) * 64;      // warp M offset (0 or 64)
    const int nrow0 = (wid & 3) * 32;       // warp N offset (0..96)
    const unsigned rtA  = (lane & 7) + ((lane >> 3) & 1) * 8;
    const unsigned s16A = ((lane >> 4) & 1) * 16;
    const unsigned rtB  = (lane & 7) + ((lane >> 4) & 1) * 8;
    const unsigned s16B = ((lane >> 3) & 1) * 16;
    const unsigned xorv = (lane & 7) * 16;

    float acc[4][4][4];
    #pragma unroll
    for (int mi = 0; mi < 4; ++mi)
        #pragma unroll
        for (int ni = 0; ni < 4; ++ni)
            #pragma unroll
            for (int r = 0; r < 4; ++r) acc[mi][ni][r] = 0.f;

    load_chunk(0, 0);
    load_chunk(1, 1);

    for (int c = 0; c < NC; ++c) {
        const int slot = c % NSLOT;
        CP_WAIT1();
        __syncthreads();
        if (c + 2 < NC) load_chunk(c + 2, (c + 2) % NSLOT);
        else            CP_COMMIT();     // empty group keeps invariant exact

        const unsigned sa = sbase + slot * STAGE_BYTES;
        const unsigned pA = sa + ST_A + (mrow0 + rtA) * 128;
        const unsigned pB = sa + ST_B + (nrow0 + rtB) * 128;

        #pragma unroll
        for (int kk = 0; kk < 4; ++kk) {
            const unsigned colA = ((unsigned)(kk * 32) + s16A) ^ xorv;
            const unsigned colB = ((unsigned)(kk * 32) + s16B) ^ xorv;
            unsigned ah[4][4], bh[2][4];
            #pragma unroll
            for (int mi = 0; mi < 4; ++mi)
                ldsm4(ah[mi][0], ah[mi][1], ah[mi][2], ah[mi][3],
                      pA + mi * 2048 + colA);
            #pragma unroll
            for (int nb = 0; nb < 2; ++nb)
                ldsm4(bh[nb][0], bh[nb][1], bh[nb][2], bh[nb][3],
                      pB + nb * 2048 + colB);
            #pragma unroll
            for (int mi = 0; mi < 4; ++mi)
                #pragma unroll
                for (int ni = 0; ni < 4; ++ni)
                    mma16816(acc[mi][ni], ah[mi], &bh[ni >> 1][(ni & 1) * 2]);
        }
    }
    CP_WAIT0();

    #pragma unroll
    for (int ni = 0; ni < 4; ++ni) {
        const int cc = col0 + nrow0 + ni * 8 + (lane & 3) * 2;
        const float b0 = bias[cc], b1 = bias[cc + 1];
        #pragma unroll
        for (int mi = 0; mi < 4; ++mi) {
            const int r = row0 + mrow0 + mi * 16 + (lane >> 2);
            if (HOUT) {
                __half* C = (__half*)Cout;
                *(__half2*)(C + (size_t)r * ldc + cc) =
                    __half2(__float2half_rn(acc[mi][ni][0] + b0),
                            __float2half_rn(acc[mi][ni][1] + b1));
                *(__half2*)(C + (size_t)(r + 8) * ldc + cc) =
                    __half2(__float2half_rn(acc[mi][ni][2] + b0),
                            __float2half_rn(acc[mi][ni][3] + b1));
            } else {
                float* C = (float*)Cout;
                *(float2*)(C + (size_t)r * ldc + cc) =
                    make_float2(acc[mi][ni][0] + b0, acc[mi][ni][1] + b1);
                *(float2*)(C + (size_t)(r + 8) * ldc + cc) =
                    make_float2(acc[mi][ni][2] + b0, acc[mi][ni][3] + b1);
            }
        }
    }
}

// ---------------------------------------------------------------------------
// Fused prologue: x->fp16 | 3x weight transpose->fp16 | ak/av proj | bias cat
// One launch; role selected by blockIdx.x range so the parts run concurrently.
// ---------------------------------------------------------------------------
__global__ __launch_bounds__(256)
void prologue(const float* __restrict__ x,  const float* __restrict__ ax,
              const float* __restrict__ WQ, const float* __restrict__ WQb,
              const float* __restrict__ WK, const float* __restrict__ WKb,
              const float* __restrict__ WV, const float* __restrict__ WVb,
              const float* __restrict__ WO)
{
    __shared__ float sh[HID + 32 * 33];   // proj xs / transpose tile
    const int bid = blockIdx.x;
    const int tid = threadIdx.x;

    if (bid < NB_TOHALF) {
        // ---- x (fp32) -> g_xhi (fp16) ----
        int i = bid * 256 + tid;
        float4 v = ((const float4*)x)[i];
        __half2* op = (__half2*)(g_xhi + (size_t)i * 4);
        op[0] = __half2(__float2half_rn(v.x), __float2half_rn(v.y));
        op[1] = __half2(__float2half_rn(v.z), __float2half_rn(v.w));
    } else if (bid < NB_TOHALF + NB_TRANS) {
        // ---- W [K,N] fp32 -> W^T fp16 [N,K] (3 weights) ----
        int idx = bid - NB_TOHALF;
        int z = idx >> 10, r = idx & 1023;
        const float* W; __half* T;
        if      (z == 0) { W = WQ; T = g_wqkT; }
        else if (z == 1) { W = WK; T = g_wqkT + (size_t)HID * Kdim; }
        else             { W = WO; T = g_woT; }
        int n0 = (r & 31) * 32, k0 = (r >> 5) * 32;
        int tx = tid & 31, ty = tid >> 5;           // (32, 8)
        float (*t)[33] = (float(*)[33])sh;
        #pragma unroll
        for (int i = 0; i < 32; i += 8)
            t[ty + i][tx] = W[(size_t)(k0 + ty + i) * HID + n0 + tx];
        __syncthreads();
        #pragma unroll
        for (int i = 0; i < 32; i += 8)
            T[(size_t)(n0 + ty + i) * Kdim + k0 + tx] =
                __float2half_rn(t[tx][ty + i]);
    } else if (bid < NB_TOHALF + NB_TRANS + NB_PROJ) {
        // ---- ak = ax@WK + bK, av = ax@WV + bV ----
        int pb  = bid - NB_TOHALF - NB_TRANS;
        int sel = pb >> 5;
        int bb  = (pb >> 2) & 7;
        int n   = ((pb & 3) << 8) + tid;
        float* xs = sh;
        for (int i = tid; i < HID; i += 256) xs[i] = ax[bb * HID + i];
        __syncthreads();
        const float* W    = sel ? WV  : WK;
        const float* bias = sel ? WVb : WKb;
        float acc = 0.f;
        #pragma unroll 8
        for (int kk = 0; kk < HID; ++kk)
            acc = fmaf(xs[kk], W[(size_t)kk * HID + n], acc);
        float* o = sel ? g_av : g_ak;
        o[bb * HID + n] = acc + bias[n];
    } else {
        // ---- bias concat: g_bqk = [WQ_b | WK_b] ----
        int i = (bid - NB_TOHALF - NB_TRANS - NB_PROJ) * 256 + tid;
        g_bqk[i] = (i < HID) ? WQb[i] : WKb[i - HID];
    }
}

// ---------------------------------------------------------------------------
// Attention, 2 heads per warp: lane = (head-half, 4 dims), 8B loads,
// 4-step shfl reductions over 16 lanes. fp16 qk in (stride NQK), fp16 out.
// ---------------------------------------------------------------------------
__global__ __launch_bounds__(256)
void attn_kernel(const __half* __restrict__ qk, __half* __restrict__ ahi)
{
    const int w    = (blockIdx.x * blockDim.x + threadIdx.x) >> 5;
    const int lane = threadIdx.x & 31;
    const int hp = w & 7;                 // head pair 0..7
    const int l  = (w >> 3) & (Lc - 1);
    const int b  = w >> 15;
    const int h  = hp * 2 + (lane >> 4);  // head 0..15
    const int li = lane & 15;             // owns dims 4*li .. 4*li+3

    const size_t tok   = (size_t)b * Lc + l;
    const int    doff  = h * HD + li * 4;
    const size_t qbase = tok * NQK + doff;
    const size_t kbase = qbase + HID;
    const size_t obase = tok * HID + doff;
    const size_t gbase = (size_t)b * HID + doff;

    float4 qv = ldh4(qk + qbase);
    float4 k0 = *(const float4*)(g_ak + gbase);
    float4 v0 = *(const float4*)(g_av + gbase);
    float4 k1 = make_float4(0.f, 0.f, 0.f, 0.f);
    float4 k3 = make_float4(0.f, 0.f, 0.f, 0.f);
    if (l > 0)      k1 = ldh4(qk + kbase - NQK);
    float4 k2 = ldh4(qk + kbase);
    if (l < Lc - 1) k3 = ldh4(qk + kbase + NQK);

    float p0 = qv.x * k0.x + qv.y * k0.y + qv.z * k0.z + qv.w * k0.w;
    float p1 = qv.x * k1.x + qv.y * k1.y + qv.z * k1.z + qv.w * k1.w;
    float p2 = qv.x * k2.x + qv.y * k2.y + qv.z * k2.z + qv.w * k2.w;
    float p3 = qv.x * k3.x + qv.y * k3.y + qv.z * k3.z + qv.w * k3.w;
    #pragma unroll
    for (int o = 8; o; o >>= 1) {          // reduce within each 16-lane half
        p0 += __shfl_xor_sync(0xFFFFFFFFu, p0, o);
        p1 += __shfl_xor_sync(0xFFFFFFFFu, p1, o);
        p2 += __shfl_xor_sync(0xFFFFFFFFu, p2, o);
        p3 += __shfl_xor_sync(0xFFFFFFFFu, p3, o);
    }
    const float scale = 0.125f;   // 1/sqrt(64)
    float s0 = p0 * scale, s1 = p1 * scale, s2 = p2 * scale, s3 = p3 * scale;
    float m = fmaxf(fmaxf(s0, s1), fmaxf(s2, s3));
    float e0 = __expf(s0 - m), e1 = __expf(s1 - m),
          e2 = __expf(s2 - m), e3 = __expf(s3 - m);
    float inv = 1.f / (e0 + e1 + e2 + e3);
    float a0 = e0 * inv, a1 = e1 * inv, a2 = e2 * inv, a3 = e3 * inv;

    float ox = a0 * v0.x + a1 * k1.x + a2 * k2.x + a3 * k3.x;
    float oy = a0 * v0.y + a1 * k1.y + a2 * k2.y + a3 * k3.y;
    float oz = a0 * v0.z + a1 * k1.z + a2 * k2.z + a3 * k3.z;
    float ow = a0 * v0.w + a1 * k1.w + a2 * k2.w + a3 * k3.w;

    uint2 o;
    __half2 lo = __half2(__float2half_rn(ox), __float2half_rn(oy));
    __half2 hi = __half2(__float2half_rn(oz), __float2half_rn(ow));
    o.x = *(unsigned*)&lo; o.y = *(unsigned*)&hi;
    *(uint2*)(ahi + obase) = o;
}

// ---------------------------------------------------------------------------
extern "C" void kernel_launch(void* const* d_in, const int* in_sizes, int n_in,
                              void* d_out, int out_size)
{
    const float* x    = (const float*)d_in[0];
    const float* ax   = (const float*)d_in[1];
    const float* WQ_w = (const float*)d_in[2];
    const float* WQ_b = (const float*)d_in[3];
    const float* WK_w = (const float*)d_in[4];
    const float* WK_b = (const float*)d_in[5];
    const float* WV_w = (const float*)d_in[6];
    const float* WV_b = (const float*)d_in[7];
    const float* WO_w = (const float*)d_in[8];
    const float* WO_b = (const float*)d_in[9];
    float* out = (float*)d_out;

    float* bqk;
    __half *qkp, *xhi, *ahi, *wqkT, *woT;
    cudaGetSymbolAddress((void**)&qkp,  g_qk);
    cudaGetSymbolAddress((void**)&bqk,  g_bqk);
    cudaGetSymbolAddress((void**)&xhi,  g_xhi);
    cudaGetSymbolAddress((void**)&ahi,  g_ahi);
    cudaGetSymbolAddress((void**)&wqkT, g_wqkT);
    cudaGetSymbolAddress((void**)&woT,  g_woT);

    cudaFuncSetAttribute((const void*)gemm_h1<true>,
                         cudaFuncAttributeMaxDynamicSharedMemorySize, SMEM_REQ);
    cudaFuncSetAttribute((const void*)gemm_h1<false>,
                         cudaFuncAttributeMaxDynamicSharedMemorySize, SMEM_REQ);

    // fused prologue (conversions + transposes + small projections + bias)
    prologue<<<NB_PRO, 256>>>(x, ax, WQ_w, WQ_b, WK_w, WK_b, WV_w, WV_b, WO_w);

    // fused Q|K projection: [MTOK, 2048] fp16, 1-pass
    dim3 gqk(NQK / BN, MTOK / BM);   // (16, 256)
    gemm_h1<true><<<gqk, 256, SMEM_REQ>>>(xhi, wqkT, bqk, qkp, NQK);

    // attention -> fp16 output (2 heads per warp)
    attn_kernel<<<(Bc * Lc * NH) / 16, 256>>>(qkp, ahi);

    // output projection (fp32 out, 1-pass)
    dim3 go(HID / BN, MTOK / BM);    // (8, 256)
    gemm_h1<false><<<go, 256, SMEM_REQ>>>(ahi, woT, WO_b, out, HID);
}